// round 1
// baseline (speedup 1.0000x reference)
#include <cuda_runtime.h>
#include <cuda_bf16.h>
#include <math.h>

// ---------------- problem constants ----------------
#define B_      8
#define N_      1024
#define DIM_    768
#define HEADS_  12
#define HDIM_   64
#define HIDDEN_ 1536
#define ROWS_   (B_ * N_)            // 8192
#define BH_     (B_ * HEADS_)        // 96

// ---------------- scratch (device globals; no runtime alloc) ----------------
__device__ float g_h   [ROWS_ * DIM_];       // LN output (reused for both norms)
__device__ float g_qkv [ROWS_ * 3 * DIM_];   // 72 MB
__device__ float g_attn[(long)BH_ * N_ * N_];// 402 MB
__device__ float g_o   [ROWS_ * DIM_];       // attention output, [B,N,C]
__device__ float g_x1  [ROWS_ * DIM_];       // x after attn residual
__device__ float g_mlp [ROWS_ * HIDDEN_];    // 48 MB

// ---------------- LayerNorm: one block per row ----------------
__global__ void ln_kernel(const float* __restrict__ x,
                          const float* __restrict__ g,
                          const float* __restrict__ b,
                          float* __restrict__ out)
{
    const int row = blockIdx.x;
    const float* xr = x + (long)row * DIM_;
    __shared__ float red[256];

    float local = 0.f;
    for (int i = threadIdx.x; i < DIM_; i += 256) local += xr[i];
    red[threadIdx.x] = local; __syncthreads();
    for (int s = 128; s > 0; s >>= 1) {
        if (threadIdx.x < s) red[threadIdx.x] += red[threadIdx.x + s];
        __syncthreads();
    }
    const float mu = red[0] * (1.f / DIM_);
    __syncthreads();

    local = 0.f;
    for (int i = threadIdx.x; i < DIM_; i += 256) {
        float d = xr[i] - mu; local += d * d;
    }
    red[threadIdx.x] = local; __syncthreads();
    for (int s = 128; s > 0; s >>= 1) {
        if (threadIdx.x < s) red[threadIdx.x] += red[threadIdx.x + s];
        __syncthreads();
    }
    const float inv = rsqrtf(red[0] * (1.f / DIM_) + 1e-5f);

    float* orow = out + (long)row * DIM_;
    for (int i = threadIdx.x; i < DIM_; i += 256)
        orow[i] = (xr[i] - mu) * inv * g[i] + b[i];
}

// ---------------- generic SGEMM: C = A[MxK] @ B[KxN] (+bias)(+gelu)(+res) ----------------
template<bool GELU>
__global__ void sgemm_kernel(const float* __restrict__ A,
                             const float* __restrict__ Bm,
                             const float* __restrict__ bias,   // [N] or null
                             const float* __restrict__ res,    // [MxN] or null
                             float* __restrict__ C,
                             int M, int N, int K)
{
    const int BM = 64, BN = 64, BK = 16;
    __shared__ float As[BK][BM + 1];
    __shared__ float Bs[BK][BN];

    const int row0 = blockIdx.y * BM;
    const int col0 = blockIdx.x * BN;
    const int tx = threadIdx.x & 15;
    const int ty = threadIdx.x >> 4;

    float acc[4][4] = {};

    for (int k0 = 0; k0 < K; k0 += BK) {
        // A tile: BMxBK, stored transposed
        for (int idx = threadIdx.x; idx < BM * BK; idx += 256) {
            int r = idx >> 4, c = idx & 15;
            As[c][r] = A[(long)(row0 + r) * K + k0 + c];
        }
        // B tile: BKxBN
        for (int idx = threadIdx.x; idx < BK * BN; idx += 256) {
            int r = idx >> 6, c = idx & 63;
            Bs[r][c] = Bm[(long)(k0 + r) * N + col0 + c];
        }
        __syncthreads();
        #pragma unroll
        for (int kk = 0; kk < BK; kk++) {
            float a[4], bb[4];
            #pragma unroll
            for (int i = 0; i < 4; i++) a[i]  = As[kk][ty * 4 + i];
            #pragma unroll
            for (int j = 0; j < 4; j++) bb[j] = Bs[kk][tx * 4 + j];
            #pragma unroll
            for (int i = 0; i < 4; i++)
                #pragma unroll
                for (int j = 0; j < 4; j++)
                    acc[i][j] += a[i] * bb[j];
        }
        __syncthreads();
    }

    #pragma unroll
    for (int i = 0; i < 4; i++) {
        const int r = row0 + ty * 4 + i;
        #pragma unroll
        for (int j = 0; j < 4; j++) {
            const int c = col0 + tx * 4 + j;
            float v = acc[i][j];
            if (bias) v += bias[c];
            if (GELU) v = 0.5f * v * (1.f + erff(v * 0.70710678118654752f));
            if (res)  v += res[(long)r * N + c];
            C[(long)r * N + c] = v;
        }
    }
}

// ---------------- attention scores: attn[b,h,i,j] = (q.k)*scale + rpe[h,i,j] ----------------
__global__ void attn_scores_kernel(const float* __restrict__ qkv,
                                   const float* __restrict__ rpe,
                                   float* __restrict__ attn)
{
    __shared__ float Qs[64][65];   // [d][i]
    __shared__ float Ks[64][65];   // [d][j]

    const int bh = blockIdx.z;
    const int b = bh / HEADS_, h = bh % HEADS_;
    const int i0 = blockIdx.y * 64;
    const int j0 = blockIdx.x * 64;

    const float* qbase = qkv + (long)b * N_ * (3 * DIM_) + h * HDIM_;
    const float* kbase = qbase + DIM_;

    for (int idx = threadIdx.x; idx < 64 * 64; idx += 256) {
        int r = idx >> 6, d = idx & 63;
        Qs[d][r] = qbase[(long)(i0 + r) * (3 * DIM_) + d];
        Ks[d][r] = kbase[(long)(j0 + r) * (3 * DIM_) + d];
    }
    __syncthreads();

    const int tx = threadIdx.x & 15;
    const int ty = threadIdx.x >> 4;
    float acc[4][4] = {};

    #pragma unroll
    for (int kk = 0; kk < 64; kk++) {
        float a[4], c[4];
        #pragma unroll
        for (int i = 0; i < 4; i++) a[i] = Qs[kk][ty * 4 + i];
        #pragma unroll
        for (int j = 0; j < 4; j++) c[j] = Ks[kk][tx * 4 + j];
        #pragma unroll
        for (int i = 0; i < 4; i++)
            #pragma unroll
            for (int j = 0; j < 4; j++)
                acc[i][j] += a[i] * c[j];
    }

    float* out = attn + (long)bh * N_ * N_;
    const float* rp = rpe + (long)h * N_ * N_;
    #pragma unroll
    for (int i = 0; i < 4; i++) {
        const int r = i0 + ty * 4 + i;
        #pragma unroll
        for (int j = 0; j < 4; j++) {
            const int c = j0 + tx * 4 + j;
            out[(long)r * N_ + c] = acc[i][j] * 0.125f + rp[(long)r * N_ + c];
        }
    }
}

// ---------------- row softmax over 1024 elements ----------------
__global__ void softmax_kernel(float* __restrict__ attn)
{
    const long row = blockIdx.x;
    float* p = attn + row * N_;
    __shared__ float red[256];

    float m = -1e30f;
    for (int i = threadIdx.x; i < N_; i += 256) m = fmaxf(m, p[i]);
    red[threadIdx.x] = m; __syncthreads();
    for (int s = 128; s > 0; s >>= 1) {
        if (threadIdx.x < s) red[threadIdx.x] = fmaxf(red[threadIdx.x], red[threadIdx.x + s]);
        __syncthreads();
    }
    const float mx = red[0];
    __syncthreads();

    float sum = 0.f;
    for (int i = threadIdx.x; i < N_; i += 256) {
        float e = expf(p[i] - mx);
        p[i] = e;
        sum += e;
    }
    red[threadIdx.x] = sum; __syncthreads();
    for (int s = 128; s > 0; s >>= 1) {
        if (threadIdx.x < s) red[threadIdx.x] += red[threadIdx.x + s];
        __syncthreads();
    }
    const float inv = 1.f / red[0];
    for (int i = threadIdx.x; i < N_; i += 256) p[i] *= inv;
}

// ---------------- PV: o[b,i,h*64+d] = sum_j attn[bh,i,j] * v[b,j,h,d] ----------------
__global__ void attn_pv_kernel(const float* __restrict__ attn,
                               const float* __restrict__ qkv,
                               float* __restrict__ o)
{
    __shared__ float As[32][65];  // [kk][i]
    __shared__ float Vs[32][64];  // [kk][d]

    const int bh = blockIdx.z;
    const int b = bh / HEADS_, h = bh % HEADS_;
    const int i0 = blockIdx.y * 64;

    const float* arow  = attn + (long)bh * N_ * N_ + (long)i0 * N_;
    const float* vbase = qkv + (long)b * N_ * (3 * DIM_) + 2 * DIM_ + h * HDIM_;

    const int tx = threadIdx.x & 15;
    const int ty = threadIdx.x >> 4;
    float acc[4][4] = {};

    for (int k0 = 0; k0 < N_; k0 += 32) {
        for (int idx = threadIdx.x; idx < 64 * 32; idx += 256) {
            int r = idx >> 5, c = idx & 31;
            As[c][r] = arow[(long)r * N_ + k0 + c];
        }
        for (int idx = threadIdx.x; idx < 32 * 64; idx += 256) {
            int r = idx >> 6, c = idx & 63;
            Vs[r][c] = vbase[(long)(k0 + r) * (3 * DIM_) + c];
        }
        __syncthreads();
        #pragma unroll
        for (int kk = 0; kk < 32; kk++) {
            float a[4], v[4];
            #pragma unroll
            for (int i = 0; i < 4; i++) a[i] = As[kk][ty * 4 + i];
            #pragma unroll
            for (int j = 0; j < 4; j++) v[j] = Vs[kk][tx * 4 + j];
            #pragma unroll
            for (int i = 0; i < 4; i++)
                #pragma unroll
                for (int j = 0; j < 4; j++)
                    acc[i][j] += a[i] * v[j];
        }
        __syncthreads();
    }

    #pragma unroll
    for (int i = 0; i < 4; i++) {
        const int n = i0 + ty * 4 + i;
        #pragma unroll
        for (int j = 0; j < 4; j++) {
            const int d = tx * 4 + j;
            o[(long)(b * N_ + n) * DIM_ + h * HDIM_ + d] = acc[i][j];
        }
    }
}

// ---------------- host ----------------
static float* symaddr(const void* sym)
{
    void* p = nullptr;
    cudaGetSymbolAddress(&p, sym);
    return (float*)p;
}

extern "C" void kernel_launch(void* const* d_in, const int* in_sizes, int n_in,
                              void* d_out, int out_size)
{
    const float* x      = (const float*)d_in[0];
    const float* rpe    = (const float*)d_in[1];
    const float* qkv_w  = (const float*)d_in[2];
    const float* proj_w = (const float*)d_in[3];
    const float* proj_b = (const float*)d_in[4];
    const float* ln1_g  = (const float*)d_in[5];
    const float* ln1_b  = (const float*)d_in[6];
    const float* ln2_g  = (const float*)d_in[7];
    const float* ln2_b  = (const float*)d_in[8];
    const float* fc1_w  = (const float*)d_in[9];
    const float* fc1_b  = (const float*)d_in[10];
    const float* fc2_w  = (const float*)d_in[11];
    const float* fc2_b  = (const float*)d_in[12];
    float* out = (float*)d_out;

    float* h    = symaddr(g_h);
    float* qkv  = symaddr(g_qkv);
    float* attn = symaddr(g_attn);
    float* o    = symaddr(g_o);
    float* x1   = symaddr(g_x1);
    float* mlp  = symaddr(g_mlp);

    dim3 blk(256);

    // 1) LN1
    ln_kernel<<<ROWS_, blk>>>(x, ln1_g, ln1_b, h);

    // 2) QKV GEMM: [8192,768]@[768,2304]
    sgemm_kernel<false><<<dim3(3 * DIM_ / 64, ROWS_ / 64), blk>>>(
        h, qkv_w, nullptr, nullptr, qkv, ROWS_, 3 * DIM_, DIM_);

    // 3) scores = QK^T*scale + rpe
    attn_scores_kernel<<<dim3(N_ / 64, N_ / 64, BH_), blk>>>(qkv, rpe, attn);

    // 4) softmax
    softmax_kernel<<<BH_ * N_, blk>>>(attn);

    // 5) PV
    attn_pv_kernel<<<dim3(1, N_ / 64, BH_), blk>>>(attn, qkv, o);

    // 6) proj + bias + residual(x)
    sgemm_kernel<false><<<dim3(DIM_ / 64, ROWS_ / 64), blk>>>(
        o, proj_w, proj_b, x, x1, ROWS_, DIM_, DIM_);

    // 7) LN2
    ln_kernel<<<ROWS_, blk>>>(x1, ln2_g, ln2_b, h);

    // 8) FC1 + bias + gelu
    sgemm_kernel<true><<<dim3(HIDDEN_ / 64, ROWS_ / 64), blk>>>(
        h, fc1_w, fc1_b, nullptr, mlp, ROWS_, HIDDEN_, DIM_);

    // 9) FC2 + bias + residual(x1) -> out
    sgemm_kernel<false><<<dim3(DIM_ / 64, ROWS_ / 64), blk>>>(
        mlp, fc2_w, fc2_b, x1, out, ROWS_, DIM_, HIDDEN_);
}

// round 2
// speedup vs baseline: 2.1645x; 2.1645x over previous
#include <cuda_runtime.h>
#include <cuda_bf16.h>
#include <math.h>
#include <stdint.h>

// ---------------- problem constants ----------------
#define B_      8
#define N_      1024
#define DIM_    768
#define HEADS_  12
#define HDIM_   64
#define HIDDEN_ 1536
#define ROWS_   (B_ * N_)            // 8192
#define BH_     (B_ * HEADS_)        // 96

// ---------------- scratch (device globals; no runtime alloc) ----------------
__device__ float g_h   [ROWS_ * DIM_];
__device__ float g_qkv [ROWS_ * 3 * DIM_];
__device__ float g_attn[(long)BH_ * N_ * N_];
__device__ float g_o   [ROWS_ * DIM_];
__device__ float g_x1  [ROWS_ * DIM_];
__device__ float g_mlp [ROWS_ * HIDDEN_];

// ---------------- tf32 helpers ----------------
__device__ __forceinline__ uint32_t f2tf32(float f)
{
    uint32_t u;
    asm("cvt.rna.tf32.f32 %0, %1;" : "=r"(u) : "f"(f));
    return u;
}

__device__ __forceinline__ void mma_tf32(float* c, const uint32_t* a, const uint32_t* b)
{
    asm volatile(
        "mma.sync.aligned.m16n8k8.row.col.f32.tf32.tf32.f32 "
        "{%0,%1,%2,%3}, {%4,%5,%6,%7}, {%8,%9}, {%0,%1,%2,%3};"
        : "+f"(c[0]), "+f"(c[1]), "+f"(c[2]), "+f"(c[3])
        : "r"(a[0]), "r"(a[1]), "r"(a[2]), "r"(a[3]),
          "r"(b[0]), "r"(b[1]));
}

// ---------------- generic tf32 MMA GEMM core ----------------
// C[M,N] = A[M,K] @ B (B row-major [K,N] if !BT, else B is [N,K] and we use B^T)
// EPI: 0 = (+bias)(+res), 1 = gelu(acc+bias), 2 = acc*scale + aux
template<int BM, int BN, int BK, int WM, int WN, bool BT, int EPI>
__device__ __forceinline__ void gemm_core(
    const float* __restrict__ A, int lda,
    const float* __restrict__ B, int ldb,
    float* __restrict__ C, int ldc,
    const float* __restrict__ bias,
    const float* __restrict__ res,
    const float* __restrict__ aux, float scale,
    int m0, int n0, int K)
{
    static_assert(BK == 32, "BK must be 32");
    constexpr int WARPS_N = BN / WN;
    constexpr int MT = WM / 16;
    constexpr int NT = WN / 8;

    __shared__ uint32_t As[BK][BM + 8];
    __shared__ uint32_t Bs[BK][BN + 8];

    const int tid  = threadIdx.x;
    const int warp = tid >> 5;
    const int lane = tid & 31;
    const int gid  = lane >> 2;   // group id 0..7
    const int tig  = lane & 3;    // thread in group 0..3
    const int wm   = (warp / WARPS_N) * WM;
    const int wn   = (warp % WARPS_N) * WN;

    float acc[MT][NT][4] = {};

    for (int k0 = 0; k0 < K; k0 += BK) {
        // ---- load A tile (BM x BK) as As[k][m], tf32-converted ----
        #pragma unroll
        for (int i = 0; i < BM * BK / 256; i++) {
            int idx = tid + i * 256;
            int k = idx & 31;
            int m = idx >> 5;
            As[k][m] = f2tf32(A[(long)(m0 + m) * lda + k0 + k]);
        }
        // ---- load B tile as Bs[k][n] ----
        if (BT) {
            #pragma unroll
            for (int i = 0; i < BN * BK / 256; i++) {
                int idx = tid + i * 256;
                int k = idx & 31;
                int n = idx >> 5;
                Bs[k][n] = f2tf32(B[(long)(n0 + n) * ldb + k0 + k]);
            }
        } else {
            #pragma unroll
            for (int i = 0; i < BN * BK / 256; i++) {
                int idx = tid + i * 256;
                int n = idx % BN;
                int k = idx / BN;
                Bs[k][n] = f2tf32(B[(long)(k0 + k) * ldb + n0 + n]);
            }
        }
        __syncthreads();

        #pragma unroll
        for (int ks = 0; ks < BK / 8; ks++) {
            const int kk = ks * 8;
            uint32_t af[MT][4], bf[NT][2];
            #pragma unroll
            for (int mt = 0; mt < MT; mt++) {
                const int mm = wm + mt * 16 + gid;
                af[mt][0] = As[kk + tig    ][mm    ];
                af[mt][1] = As[kk + tig    ][mm + 8];
                af[mt][2] = As[kk + tig + 4][mm    ];
                af[mt][3] = As[kk + tig + 4][mm + 8];
            }
            #pragma unroll
            for (int nt = 0; nt < NT; nt++) {
                const int nn = wn + nt * 8 + gid;
                bf[nt][0] = Bs[kk + tig    ][nn];
                bf[nt][1] = Bs[kk + tig + 4][nn];
            }
            #pragma unroll
            for (int mt = 0; mt < MT; mt++)
                #pragma unroll
                for (int nt = 0; nt < NT; nt++)
                    mma_tf32(acc[mt][nt], af[mt], bf[nt]);
        }
        __syncthreads();
    }

    // ---- epilogue ----
    #pragma unroll
    for (int mt = 0; mt < MT; mt++) {
        #pragma unroll
        for (int nt = 0; nt < NT; nt++) {
            #pragma unroll
            for (int half = 0; half < 2; half++) {
                const int r = m0 + wm + mt * 16 + gid + half * 8;
                const int c = n0 + wn + nt * 8 + tig * 2;
                float v0 = acc[mt][nt][half * 2 + 0];
                float v1 = acc[mt][nt][half * 2 + 1];
                if (EPI == 2) {
                    v0 = v0 * scale + aux[(long)r * ldc + c];
                    v1 = v1 * scale + aux[(long)r * ldc + c + 1];
                } else {
                    if (bias) { v0 += bias[c]; v1 += bias[c + 1]; }
                    if (EPI == 1) {
                        v0 = 0.5f * v0 * (1.f + erff(v0 * 0.70710678118654752f));
                        v1 = 0.5f * v1 * (1.f + erff(v1 * 0.70710678118654752f));
                    }
                    if (res) {
                        v0 += res[(long)r * ldc + c];
                        v1 += res[(long)r * ldc + c + 1];
                    }
                }
                C[(long)r * ldc + c    ] = v0;
                C[(long)r * ldc + c + 1] = v1;
            }
        }
    }
}

// ---------------- dense GEMM wrapper ----------------
template<int EPI>
__global__ void __launch_bounds__(256)
dense_gemm(const float* __restrict__ A, int lda,
           const float* __restrict__ B, int ldb,
           float* __restrict__ C, int ldc,
           const float* __restrict__ bias,
           const float* __restrict__ res,
           int K)
{
    gemm_core<128, 128, 32, 64, 32, false, EPI>(
        A, lda, B, ldb, C, ldc, bias, res, nullptr, 0.f,
        blockIdx.y * 128, blockIdx.x * 128, K);
}

// ---------------- attention scores: attn = (Q @ K^T)*scale + rpe ----------------
__global__ void __launch_bounds__(256)
scores_gemm(const float* __restrict__ qkv,
            const float* __restrict__ rpe,
            float* __restrict__ attn)
{
    const int z = blockIdx.z;
    const int b = z / HEADS_, h = z % HEADS_;
    const float* A = qkv + (long)b * N_ * (3 * DIM_) + h * HDIM_;          // Q rows
    const float* B = A + DIM_;                                            // K rows
    float* C = attn + (long)z * N_ * N_;
    const float* aux = rpe + (long)h * N_ * N_;
    gemm_core<128, 128, 32, 64, 32, true, 2>(
        A, 3 * DIM_, B, 3 * DIM_, C, N_, nullptr, nullptr, aux, 0.125f,
        blockIdx.y * 128, blockIdx.x * 128, HDIM_);
}

// ---------------- PV: o = attn @ V ----------------
__global__ void __launch_bounds__(256)
pv_gemm(const float* __restrict__ attn,
        const float* __restrict__ qkv,
        float* __restrict__ o)
{
    const int z = blockIdx.z;
    const int b = z / HEADS_, h = z % HEADS_;
    const float* A = attn + (long)z * N_ * N_;
    const float* B = qkv + (long)b * N_ * (3 * DIM_) + 2 * DIM_ + h * HDIM_;  // V rows
    float* C = o + (long)b * N_ * DIM_ + h * HDIM_;
    gemm_core<128, 64, 32, 32, 32, false, 0>(
        A, N_, B, 3 * DIM_, C, DIM_, nullptr, nullptr, nullptr, 0.f,
        blockIdx.y * 128, 0, N_);
}

// ---------------- LayerNorm: one block per row ----------------
__global__ void ln_kernel(const float* __restrict__ x,
                          const float* __restrict__ g,
                          const float* __restrict__ b,
                          float* __restrict__ out)
{
    const int row = blockIdx.x;
    const float* xr = x + (long)row * DIM_;
    const int tid = threadIdx.x;
    __shared__ float sm[8];

    // DIM_=768, 256 threads -> 3 elements each
    float v0 = xr[tid], v1 = xr[tid + 256], v2 = xr[tid + 512];
    float s = v0 + v1 + v2;
    #pragma unroll
    for (int o = 16; o; o >>= 1) s += __shfl_xor_sync(~0u, s, o);
    if ((tid & 31) == 0) sm[tid >> 5] = s;
    __syncthreads();
    s = sm[0];
    #pragma unroll
    for (int i = 1; i < 8; i++) s += sm[i];
    const float mu = s * (1.f / DIM_);
    __syncthreads();

    float d0 = v0 - mu, d1 = v1 - mu, d2 = v2 - mu;
    s = d0 * d0 + d1 * d1 + d2 * d2;
    #pragma unroll
    for (int o = 16; o; o >>= 1) s += __shfl_xor_sync(~0u, s, o);
    if ((tid & 31) == 0) sm[tid >> 5] = s;
    __syncthreads();
    s = sm[0];
    #pragma unroll
    for (int i = 1; i < 8; i++) s += sm[i];
    const float inv = rsqrtf(s * (1.f / DIM_) + 1e-5f);

    float* orow = out + (long)row * DIM_;
    orow[tid      ] = d0 * inv * g[tid      ] + b[tid      ];
    orow[tid + 256] = d1 * inv * g[tid + 256] + b[tid + 256];
    orow[tid + 512] = d2 * inv * g[tid + 512] + b[tid + 512];
}

// ---------------- single-pass register softmax over 1024 elements ----------------
__global__ void softmax_kernel(float* __restrict__ attn)
{
    const long row = blockIdx.x;
    float4* p = reinterpret_cast<float4*>(attn + row * N_);
    const int tid = threadIdx.x;
    __shared__ float sm[8];

    float4 v = p[tid];
    float m = fmaxf(fmaxf(v.x, v.y), fmaxf(v.z, v.w));
    #pragma unroll
    for (int o = 16; o; o >>= 1) m = fmaxf(m, __shfl_xor_sync(~0u, m, o));
    if ((tid & 31) == 0) sm[tid >> 5] = m;
    __syncthreads();
    m = sm[0];
    #pragma unroll
    for (int i = 1; i < 8; i++) m = fmaxf(m, sm[i]);
    __syncthreads();

    v.x = expf(v.x - m);
    v.y = expf(v.y - m);
    v.z = expf(v.z - m);
    v.w = expf(v.w - m);
    float s = v.x + v.y + v.z + v.w;
    #pragma unroll
    for (int o = 16; o; o >>= 1) s += __shfl_xor_sync(~0u, s, o);
    if ((tid & 31) == 0) sm[tid >> 5] = s;
    __syncthreads();
    s = sm[0];
    #pragma unroll
    for (int i = 1; i < 8; i++) s += sm[i];
    const float inv = 1.f / s;

    v.x *= inv; v.y *= inv; v.z *= inv; v.w *= inv;
    p[tid] = v;
}

// ---------------- host ----------------
static float* symaddr(const void* sym)
{
    void* p = nullptr;
    cudaGetSymbolAddress(&p, sym);
    return (float*)p;
}

extern "C" void kernel_launch(void* const* d_in, const int* in_sizes, int n_in,
                              void* d_out, int out_size)
{
    const float* x      = (const float*)d_in[0];
    const float* rpe    = (const float*)d_in[1];
    const float* qkv_w  = (const float*)d_in[2];
    const float* proj_w = (const float*)d_in[3];
    const float* proj_b = (const float*)d_in[4];
    const float* ln1_g  = (const float*)d_in[5];
    const float* ln1_b  = (const float*)d_in[6];
    const float* ln2_g  = (const float*)d_in[7];
    const float* ln2_b  = (const float*)d_in[8];
    const float* fc1_w  = (const float*)d_in[9];
    const float* fc1_b  = (const float*)d_in[10];
    const float* fc2_w  = (const float*)d_in[11];
    const float* fc2_b  = (const float*)d_in[12];
    float* out = (float*)d_out;

    float* h    = symaddr(g_h);
    float* qkv  = symaddr(g_qkv);
    float* attn = symaddr(g_attn);
    float* o    = symaddr(g_o);
    float* x1   = symaddr(g_x1);
    float* mlp  = symaddr(g_mlp);

    dim3 blk(256);

    // 1) LN1
    ln_kernel<<<ROWS_, blk>>>(x, ln1_g, ln1_b, h);

    // 2) QKV GEMM: [8192,768]@[768,2304]
    dense_gemm<0><<<dim3(3 * DIM_ / 128, ROWS_ / 128), blk>>>(
        h, DIM_, qkv_w, 3 * DIM_, qkv, 3 * DIM_, nullptr, nullptr, DIM_);

    // 3) scores = QK^T * 0.125 + rpe
    scores_gemm<<<dim3(N_ / 128, N_ / 128, BH_), blk>>>(qkv, rpe, attn);

    // 4) softmax
    softmax_kernel<<<BH_ * N_, blk>>>(attn);

    // 5) PV
    pv_gemm<<<dim3(1, N_ / 128, BH_), blk>>>(attn, qkv, o);

    // 6) proj + bias + residual(x)
    dense_gemm<0><<<dim3(DIM_ / 128, ROWS_ / 128), blk>>>(
        o, DIM_, proj_w, DIM_, x1, DIM_, proj_b, x, DIM_);

    // 7) LN2
    ln_kernel<<<ROWS_, blk>>>(x1, ln2_g, ln2_b, h);

    // 8) FC1 + bias + gelu
    dense_gemm<1><<<dim3(HIDDEN_ / 128, ROWS_ / 128), blk>>>(
        h, DIM_, fc1_w, HIDDEN_, mlp, HIDDEN_, fc1_b, nullptr, DIM_);

    // 9) FC2 + bias + residual(x1) -> out
    dense_gemm<0><<<dim3(DIM_ / 128, ROWS_ / 128), blk>>>(
        mlp, HIDDEN_, fc2_w, DIM_, out, DIM_, fc2_b, x1, HIDDEN_);
}

// round 3
// speedup vs baseline: 2.8010x; 1.2940x over previous
#include <cuda_runtime.h>
#include <cuda_bf16.h>
#include <math.h>
#include <stdint.h>

// ---------------- problem constants ----------------
#define B_      8
#define N_      1024
#define DIM_    768
#define HEADS_  12
#define HDIM_   64
#define HIDDEN_ 1536
#define ROWS_   (B_ * N_)            // 8192
#define BH_     (B_ * HEADS_)        // 96

// ---------------- scratch (device globals; no runtime alloc) ----------------
__device__ float g_h   [ROWS_ * DIM_];
__device__ float g_qkv [ROWS_ * 3 * DIM_];
__device__ float g_o   [ROWS_ * DIM_];
__device__ float g_x1  [ROWS_ * DIM_];
__device__ float g_mlp [ROWS_ * HIDDEN_];

// ---------------- tf32 helpers ----------------
__device__ __forceinline__ uint32_t f2tf32(float f)
{
    uint32_t u;
    asm("cvt.rna.tf32.f32 %0, %1;" : "=r"(u) : "f"(f));
    return u;
}

__device__ __forceinline__ void mma_tf32(float* c, const uint32_t* a, const uint32_t* b)
{
    asm volatile(
        "mma.sync.aligned.m16n8k8.row.col.f32.tf32.tf32.f32 "
        "{%0,%1,%2,%3}, {%4,%5,%6,%7}, {%8,%9}, {%0,%1,%2,%3};"
        : "+f"(c[0]), "+f"(c[1]), "+f"(c[2]), "+f"(c[3])
        : "r"(a[0]), "r"(a[1]), "r"(a[2]), "r"(a[3]),
          "r"(b[0]), "r"(b[1]));
}

// ---------------- generic tf32 MMA GEMM core (dense layers) ----------------
template<int BM, int BN, int BK, int WM, int WN, int EPI>
__device__ __forceinline__ void gemm_core(
    const float* __restrict__ A, int lda,
    const float* __restrict__ B, int ldb,
    float* __restrict__ C, int ldc,
    const float* __restrict__ bias,
    const float* __restrict__ res,
    int m0, int n0, int K)
{
    static_assert(BK == 32, "BK must be 32");
    constexpr int WARPS_N = BN / WN;
    constexpr int MT = WM / 16;
    constexpr int NT = WN / 8;

    __shared__ uint32_t As[BK][BM + 8];
    __shared__ uint32_t Bs[BK][BN + 8];

    const int tid  = threadIdx.x;
    const int warp = tid >> 5;
    const int lane = tid & 31;
    const int gid  = lane >> 2;
    const int tig  = lane & 3;
    const int wm   = (warp / WARPS_N) * WM;
    const int wn   = (warp % WARPS_N) * WN;

    float acc[MT][NT][4] = {};

    for (int k0 = 0; k0 < K; k0 += BK) {
        #pragma unroll
        for (int i = 0; i < BM * BK / 256; i++) {
            int idx = tid + i * 256;
            int k = idx & 31;
            int m = idx >> 5;
            As[k][m] = f2tf32(A[(long)(m0 + m) * lda + k0 + k]);
        }
        #pragma unroll
        for (int i = 0; i < BN * BK / 256; i++) {
            int idx = tid + i * 256;
            int n = idx % BN;
            int k = idx / BN;
            Bs[k][n] = f2tf32(B[(long)(k0 + k) * ldb + n0 + n]);
        }
        __syncthreads();

        #pragma unroll
        for (int ks = 0; ks < BK / 8; ks++) {
            const int kk = ks * 8;
            uint32_t af[MT][4], bf[NT][2];
            #pragma unroll
            for (int mt = 0; mt < MT; mt++) {
                const int mm = wm + mt * 16 + gid;
                af[mt][0] = As[kk + tig    ][mm    ];
                af[mt][1] = As[kk + tig    ][mm + 8];
                af[mt][2] = As[kk + tig + 4][mm    ];
                af[mt][3] = As[kk + tig + 4][mm + 8];
            }
            #pragma unroll
            for (int nt = 0; nt < NT; nt++) {
                const int nn = wn + nt * 8 + gid;
                bf[nt][0] = Bs[kk + tig    ][nn];
                bf[nt][1] = Bs[kk + tig + 4][nn];
            }
            #pragma unroll
            for (int mt = 0; mt < MT; mt++)
                #pragma unroll
                for (int nt = 0; nt < NT; nt++)
                    mma_tf32(acc[mt][nt], af[mt], bf[nt]);
        }
        __syncthreads();
    }

    #pragma unroll
    for (int mt = 0; mt < MT; mt++) {
        #pragma unroll
        for (int nt = 0; nt < NT; nt++) {
            #pragma unroll
            for (int half = 0; half < 2; half++) {
                const int r = m0 + wm + mt * 16 + gid + half * 8;
                const int c = n0 + wn + nt * 8 + tig * 2;
                float v0 = acc[mt][nt][half * 2 + 0];
                float v1 = acc[mt][nt][half * 2 + 1];
                if (bias) { v0 += bias[c]; v1 += bias[c + 1]; }
                if (EPI == 1) {
                    v0 = 0.5f * v0 * (1.f + erff(v0 * 0.70710678118654752f));
                    v1 = 0.5f * v1 * (1.f + erff(v1 * 0.70710678118654752f));
                }
                if (res) {
                    v0 += res[(long)r * ldc + c];
                    v1 += res[(long)r * ldc + c + 1];
                }
                C[(long)r * ldc + c    ] = v0;
                C[(long)r * ldc + c + 1] = v1;
            }
        }
    }
}

template<int EPI>
__global__ void __launch_bounds__(256)
dense_gemm(const float* __restrict__ A, int lda,
           const float* __restrict__ B, int ldb,
           float* __restrict__ C, int ldc,
           const float* __restrict__ bias,
           const float* __restrict__ res,
           int K)
{
    gemm_core<128, 128, 32, 64, 32, EPI>(
        A, lda, B, ldb, C, ldc, bias, res,
        blockIdx.y * 128, blockIdx.x * 128, K);
}

// ---------------- fused flash attention ----------------
// One CTA per (bh, 128-row Q tile). 256 threads = 8 warps; warp w owns rows
// [16w, 16w+16). Q fragments in registers; K/V tiles in smem (tf32);
// S = Q@K^T via mma; epilogue adds rpe; online softmax in regs; P staged
// through smem (fragment-layout fixup); O accumulated by mma.
#define KS_W 68
#define VS_W 72
#define PS_W 132
#define FLASH_SMEM ((128 * KS_W + 128 * VS_W + 128 * PS_W) * 4)

__global__ void __launch_bounds__(256, 1)
flash_attn_kernel(const float* __restrict__ qkv,
                  const float* __restrict__ rpe,
                  float* __restrict__ o)
{
    extern __shared__ uint32_t sh[];
    uint32_t* Ks = sh;                    // [128][KS_W]
    uint32_t* Vs = Ks + 128 * KS_W;       // [128][VS_W]
    uint32_t* Ps = Vs + 128 * VS_W;       // [128][PS_W]

    const int bh = blockIdx.x;
    const int b  = bh / HEADS_, h = bh % HEADS_;
    const int i0 = blockIdx.y * 128;

    const int tid  = threadIdx.x;
    const int warp = tid >> 5;
    const int lane = tid & 31;
    const int gid  = lane >> 2;
    const int tig  = lane & 3;
    const int rw   = warp * 16;

    const long strideQ = 3 * DIM_;
    const float* Qp = qkv + (long)b * N_ * strideQ + h * HDIM_;
    const float* Kp = Qp + DIM_;
    const float* Vp = Qp + 2 * DIM_;

    // ---- Q fragments (held for the whole kernel) ----
    uint32_t qa[8][4];
    {
        const float* q0 = Qp + (long)(i0 + rw + gid) * strideQ;
        const float* q1 = q0 + 8 * strideQ;
        #pragma unroll
        for (int kb = 0; kb < 8; kb++) {
            const int c = kb * 8 + tig;
            qa[kb][0] = f2tf32(q0[c]);
            qa[kb][1] = f2tf32(q1[c]);
            qa[kb][2] = f2tf32(q0[c + 4]);
            qa[kb][3] = f2tf32(q1[c + 4]);
        }
    }

    float oacc[8][4] = {};
    float m_lo = -1e30f, m_hi = -1e30f;
    float l_lo = 0.f, l_hi = 0.f;

    const float* rpe_row = rpe + (long)h * N_ * N_ + (long)(i0 + rw + gid) * N_;

    for (int j0 = 0; j0 < N_; j0 += 128) {
        __syncthreads();   // previous PV done before K/V/P overwrite

        // ---- fill K/V tiles (coalesced float4, tf32-converted) ----
        #pragma unroll
        for (int i = 0; i < 8; i++) {
            const int idx = tid + i * 256;          // 0..2047
            const int j = idx >> 4;
            const int d = (idx & 15) * 4;
            const float4 kv = *(const float4*)(Kp + (long)(j0 + j) * strideQ + d);
            Ks[j * KS_W + d + 0] = f2tf32(kv.x);
            Ks[j * KS_W + d + 1] = f2tf32(kv.y);
            Ks[j * KS_W + d + 2] = f2tf32(kv.z);
            Ks[j * KS_W + d + 3] = f2tf32(kv.w);
            const float4 vv = *(const float4*)(Vp + (long)(j0 + j) * strideQ + d);
            Vs[j * VS_W + d + 0] = f2tf32(vv.x);
            Vs[j * VS_W + d + 1] = f2tf32(vv.y);
            Vs[j * VS_W + d + 2] = f2tf32(vv.z);
            Vs[j * VS_W + d + 3] = f2tf32(vv.w);
        }
        __syncthreads();

        // ---- S = Q @ K^T (per warp: 16 x 128) ----
        float s[16][4] = {};
        #pragma unroll
        for (int kb = 0; kb < 8; kb++) {
            #pragma unroll
            for (int nt = 0; nt < 16; nt++) {
                uint32_t bf[2];
                bf[0] = Ks[(nt * 8 + gid) * KS_W + kb * 8 + tig];
                bf[1] = Ks[(nt * 8 + gid) * KS_W + kb * 8 + tig + 4];
                mma_tf32(s[nt], qa[kb], bf);
            }
        }

        // ---- scale + rpe, row max ----
        float mx0 = -1e30f, mx1 = -1e30f;
        #pragma unroll
        for (int nt = 0; nt < 16; nt++) {
            const int c = j0 + nt * 8 + tig * 2;
            s[nt][0] = s[nt][0] * 0.125f + rpe_row[c];
            s[nt][1] = s[nt][1] * 0.125f + rpe_row[c + 1];
            s[nt][2] = s[nt][2] * 0.125f + rpe_row[8 * N_ + c];
            s[nt][3] = s[nt][3] * 0.125f + rpe_row[8 * N_ + c + 1];
            mx0 = fmaxf(mx0, fmaxf(s[nt][0], s[nt][1]));
            mx1 = fmaxf(mx1, fmaxf(s[nt][2], s[nt][3]));
        }
        mx0 = fmaxf(mx0, __shfl_xor_sync(~0u, mx0, 1));
        mx0 = fmaxf(mx0, __shfl_xor_sync(~0u, mx0, 2));
        mx1 = fmaxf(mx1, __shfl_xor_sync(~0u, mx1, 1));
        mx1 = fmaxf(mx1, __shfl_xor_sync(~0u, mx1, 2));

        const float mn0 = fmaxf(m_lo, mx0);
        const float mn1 = fmaxf(m_hi, mx1);
        const float f0 = __expf(m_lo - mn0);
        const float f1 = __expf(m_hi - mn1);
        m_lo = mn0; m_hi = mn1;

        // ---- exp, row sum, stage P to smem ----
        float sum0 = 0.f, sum1 = 0.f;
        #pragma unroll
        for (int nt = 0; nt < 16; nt++) {
            const float p0 = __expf(s[nt][0] - m_lo);
            const float p1 = __expf(s[nt][1] - m_lo);
            const float p2 = __expf(s[nt][2] - m_hi);
            const float p3 = __expf(s[nt][3] - m_hi);
            sum0 += p0 + p1;
            sum1 += p2 + p3;
            const int c = nt * 8 + tig * 2;
            Ps[(c    ) * PS_W + rw + gid    ] = f2tf32(p0);
            Ps[(c + 1) * PS_W + rw + gid    ] = f2tf32(p1);
            Ps[(c    ) * PS_W + rw + gid + 8] = f2tf32(p2);
            Ps[(c + 1) * PS_W + rw + gid + 8] = f2tf32(p3);
        }
        sum0 += __shfl_xor_sync(~0u, sum0, 1);
        sum0 += __shfl_xor_sync(~0u, sum0, 2);
        sum1 += __shfl_xor_sync(~0u, sum1, 1);
        sum1 += __shfl_xor_sync(~0u, sum1, 2);
        l_lo = l_lo * f0 + sum0;
        l_hi = l_hi * f1 + sum1;

        // ---- rescale O accumulator ----
        #pragma unroll
        for (int nt = 0; nt < 8; nt++) {
            oacc[nt][0] *= f0; oacc[nt][1] *= f0;
            oacc[nt][2] *= f1; oacc[nt][3] *= f1;
        }
        __syncthreads();   // Ps visible

        // ---- O += P @ V (per warp: 16 x 64, K = 128) ----
        #pragma unroll
        for (int kb = 0; kb < 16; kb++) {
            uint32_t pa[4];
            pa[0] = Ps[(kb * 8 + tig    ) * PS_W + rw + gid    ];
            pa[1] = Ps[(kb * 8 + tig    ) * PS_W + rw + gid + 8];
            pa[2] = Ps[(kb * 8 + tig + 4) * PS_W + rw + gid    ];
            pa[3] = Ps[(kb * 8 + tig + 4) * PS_W + rw + gid + 8];
            #pragma unroll
            for (int nt = 0; nt < 8; nt++) {
                uint32_t bf[2];
                bf[0] = Vs[(kb * 8 + tig    ) * VS_W + nt * 8 + gid];
                bf[1] = Vs[(kb * 8 + tig + 4) * VS_W + nt * 8 + gid];
                mma_tf32(oacc[nt], pa, bf);
            }
        }
    }

    // ---- finalize: O /= l, write [B,N,C] ----
    const float inv0 = 1.f / l_lo;
    const float inv1 = 1.f / l_hi;
    float* op0 = o + ((long)b * N_ + i0 + rw + gid) * DIM_ + h * HDIM_;
    float* op1 = op0 + 8 * DIM_;
    #pragma unroll
    for (int nt = 0; nt < 8; nt++) {
        const int c = nt * 8 + tig * 2;
        op0[c    ] = oacc[nt][0] * inv0;
        op0[c + 1] = oacc[nt][1] * inv0;
        op1[c    ] = oacc[nt][2] * inv1;
        op1[c + 1] = oacc[nt][3] * inv1;
    }
}

// ---------------- LayerNorm: one block per row ----------------
__global__ void ln_kernel(const float* __restrict__ x,
                          const float* __restrict__ g,
                          const float* __restrict__ b,
                          float* __restrict__ out)
{
    const int row = blockIdx.x;
    const float* xr = x + (long)row * DIM_;
    const int tid = threadIdx.x;
    __shared__ float sm[8];

    float v0 = xr[tid], v1 = xr[tid + 256], v2 = xr[tid + 512];
    float s = v0 + v1 + v2;
    #pragma unroll
    for (int o = 16; o; o >>= 1) s += __shfl_xor_sync(~0u, s, o);
    if ((tid & 31) == 0) sm[tid >> 5] = s;
    __syncthreads();
    s = sm[0];
    #pragma unroll
    for (int i = 1; i < 8; i++) s += sm[i];
    const float mu = s * (1.f / DIM_);
    __syncthreads();

    float d0 = v0 - mu, d1 = v1 - mu, d2 = v2 - mu;
    s = d0 * d0 + d1 * d1 + d2 * d2;
    #pragma unroll
    for (int o = 16; o; o >>= 1) s += __shfl_xor_sync(~0u, s, o);
    if ((tid & 31) == 0) sm[tid >> 5] = s;
    __syncthreads();
    s = sm[0];
    #pragma unroll
    for (int i = 1; i < 8; i++) s += sm[i];
    const float inv = rsqrtf(s * (1.f / DIM_) + 1e-5f);

    float* orow = out + (long)row * DIM_;
    orow[tid      ] = d0 * inv * g[tid      ] + b[tid      ];
    orow[tid + 256] = d1 * inv * g[tid + 256] + b[tid + 256];
    orow[tid + 512] = d2 * inv * g[tid + 512] + b[tid + 512];
}

// ---------------- host ----------------
static float* symaddr(const void* sym)
{
    void* p = nullptr;
    cudaGetSymbolAddress(&p, sym);
    return (float*)p;
}

extern "C" void kernel_launch(void* const* d_in, const int* in_sizes, int n_in,
                              void* d_out, int out_size)
{
    const float* x      = (const float*)d_in[0];
    const float* rpe    = (const float*)d_in[1];
    const float* qkv_w  = (const float*)d_in[2];
    const float* proj_w = (const float*)d_in[3];
    const float* proj_b = (const float*)d_in[4];
    const float* ln1_g  = (const float*)d_in[5];
    const float* ln1_b  = (const float*)d_in[6];
    const float* ln2_g  = (const float*)d_in[7];
    const float* ln2_b  = (const float*)d_in[8];
    const float* fc1_w  = (const float*)d_in[9];
    const float* fc1_b  = (const float*)d_in[10];
    const float* fc2_w  = (const float*)d_in[11];
    const float* fc2_b  = (const float*)d_in[12];
    float* out = (float*)d_out;

    float* h    = symaddr(g_h);
    float* qkv  = symaddr(g_qkv);
    float* o    = symaddr(g_o);
    float* x1   = symaddr(g_x1);
    float* mlp  = symaddr(g_mlp);

    cudaFuncSetAttribute(flash_attn_kernel,
                         cudaFuncAttributeMaxDynamicSharedMemorySize, FLASH_SMEM);

    dim3 blk(256);

    // 1) LN1
    ln_kernel<<<ROWS_, blk>>>(x, ln1_g, ln1_b, h);

    // 2) QKV GEMM
    dense_gemm<0><<<dim3(3 * DIM_ / 128, ROWS_ / 128), blk>>>(
        h, DIM_, qkv_w, 3 * DIM_, qkv, 3 * DIM_, nullptr, nullptr, DIM_);

    // 3) fused attention (scores + softmax + PV)
    flash_attn_kernel<<<dim3(BH_, N_ / 128), blk, FLASH_SMEM>>>(qkv, rpe, o);

    // 4) proj + bias + residual(x)
    dense_gemm<0><<<dim3(DIM_ / 128, ROWS_ / 128), blk>>>(
        o, DIM_, proj_w, DIM_, x1, DIM_, proj_b, x, DIM_);

    // 5) LN2
    ln_kernel<<<ROWS_, blk>>>(x1, ln2_g, ln2_b, h);

    // 6) FC1 + bias + gelu
    dense_gemm<1><<<dim3(HIDDEN_ / 128, ROWS_ / 128), blk>>>(
        h, DIM_, fc1_w, HIDDEN_, mlp, HIDDEN_, fc1_b, nullptr, DIM_);

    // 7) FC2 + bias + residual(x1) -> out
    dense_gemm<0><<<dim3(DIM_ / 128, ROWS_ / 128), blk>>>(
        mlp, HIDDEN_, fc2_w, DIM_, out, DIM_, fc2_b, x1, HIDDEN_);
}

// round 4
// speedup vs baseline: 4.9487x; 1.7668x over previous
#include <cuda_runtime.h>
#include <cuda_bf16.h>
#include <math.h>
#include <stdint.h>

// ---------------- problem constants ----------------
#define B_      8
#define N_      1024
#define DIM_    768
#define HEADS_  12
#define HDIM_   64
#define HIDDEN_ 1536
#define ROWS_   (B_ * N_)            // 8192
#define BH_     (B_ * HEADS_)        // 96

// ---------------- scratch (device globals; no runtime alloc) ----------------
__device__ __nv_bfloat16 g_h_bf [ROWS_ * DIM_];      // LN output (bf16)
__device__ float         g_qkv  [ROWS_ * 3 * DIM_];  // fp32 (attention input)
__device__ __nv_bfloat16 g_o_bf [ROWS_ * DIM_];      // attention out (bf16)
__device__ float         g_x1   [ROWS_ * DIM_];      // residual stream fp32
__device__ __nv_bfloat16 g_mlp  [ROWS_ * HIDDEN_];   // gelu out (bf16)
// transposed bf16 weights [N][K]
__device__ __nv_bfloat16 g_wqkv [3 * DIM_ * DIM_];
__device__ __nv_bfloat16 g_wproj[DIM_ * DIM_];
__device__ __nv_bfloat16 g_wfc1 [HIDDEN_ * DIM_];
__device__ __nv_bfloat16 g_wfc2 [DIM_ * HIDDEN_];

// ---------------- helpers ----------------
__device__ __forceinline__ uint32_t f2tf32(float f)
{
    uint32_t u;
    asm("cvt.rna.tf32.f32 %0, %1;" : "=r"(u) : "f"(f));
    return u;
}

__device__ __forceinline__ void mma_tf32(float* c, const uint32_t* a, const uint32_t* b)
{
    asm volatile(
        "mma.sync.aligned.m16n8k8.row.col.f32.tf32.tf32.f32 "
        "{%0,%1,%2,%3}, {%4,%5,%6,%7}, {%8,%9}, {%0,%1,%2,%3};"
        : "+f"(c[0]), "+f"(c[1]), "+f"(c[2]), "+f"(c[3])
        : "r"(a[0]), "r"(a[1]), "r"(a[2]), "r"(a[3]),
          "r"(b[0]), "r"(b[1]));
}

__device__ __forceinline__ void mma_bf16(float* c, const uint32_t* a, const uint32_t* b)
{
    asm volatile(
        "mma.sync.aligned.m16n8k16.row.col.f32.bf16.bf16.f32 "
        "{%0,%1,%2,%3}, {%4,%5,%6,%7}, {%8,%9}, {%0,%1,%2,%3};"
        : "+f"(c[0]), "+f"(c[1]), "+f"(c[2]), "+f"(c[3])
        : "r"(a[0]), "r"(a[1]), "r"(a[2]), "r"(a[3]),
          "r"(b[0]), "r"(b[1]));
}

__device__ __forceinline__ void cp16(uint32_t dst, const void* src)
{
    asm volatile("cp.async.cg.shared.global [%0], [%1], 16;" :: "r"(dst), "l"(src));
}

// ---------------- weight prep: fp32 [K][N] -> bf16 [N][K] ----------------
__global__ void wprep(const float* __restrict__ w, __nv_bfloat16* __restrict__ wt,
                      int K, int N)
{
    __shared__ float t[32][33];
    const int n0 = blockIdx.x * 32, k0 = blockIdx.y * 32;
    const int tx = threadIdx.x, ty = threadIdx.y;   // 32 x 8
    #pragma unroll
    for (int i = 0; i < 32; i += 8)
        t[ty + i][tx] = w[(long)(k0 + ty + i) * N + n0 + tx];
    __syncthreads();
    #pragma unroll
    for (int i = 0; i < 32; i += 8)
        wt[(long)(n0 + ty + i) * K + k0 + tx] = __float2bfloat16(t[tx][ty + i]);
}

// ---------------- bf16 pipelined GEMM ----------------
// C[M,N] = A[M,K](bf16) @ Bt[N,K](bf16)^T, BM=BN=128, BK=32, 256 thr, 8 warps
// GELU: apply gelu(acc+bias); OUTBF: write bf16 else fp32 (+bias)(+res)
#define GW 20            // smem words per 32-k row (16 data + 4 pad)
#define TILE_W (128 * GW)
#define BGEMM_SMEM (4 * TILE_W * 4)   // 2 bufs x (A+B) = 40960 B

template<bool GELU, bool OUTBF>
__global__ void __launch_bounds__(256)
bgemm(const __nv_bfloat16* __restrict__ A, int lda,
      const __nv_bfloat16* __restrict__ Bt, int ldb,
      void* __restrict__ Cv, int ldc,
      const float* __restrict__ bias,
      const float* __restrict__ res,
      int K)
{
    extern __shared__ uint32_t sm[];
    const uint32_t smem_base = (uint32_t)__cvta_generic_to_shared(sm);

    const int m0 = blockIdx.y * 128;
    const int n0 = blockIdx.x * 128;
    const int tid  = threadIdx.x;
    const int warp = tid >> 5;
    const int lane = tid & 31;
    const int gid  = lane >> 2;
    const int tig  = lane & 3;
    const int wm   = (warp >> 2) * 64;   // 2x4 warp grid
    const int wn   = (warp & 3) * 32;

    const int lm = tid >> 2;        // row handled by this thread (2 rows: lm, lm+64? no)
    const int ch = tid & 3;         // 16B chunk within row

    float acc[4][4][4] = {};

    const __nv_bfloat16* Ag = A + (long)m0 * lda;
    const __nv_bfloat16* Bg = Bt + (long)n0 * ldb;

    auto issue = [&](int k0, int buf) {
        const uint32_t dA = smem_base + (buf * TILE_W) * 4;
        const uint32_t dB = smem_base + (2 * TILE_W + buf * TILE_W) * 4;
        #pragma unroll
        for (int i = 0; i < 2; i++) {
            const int m = lm + i * 64;
            cp16(dA + (m * GW + ch * 4) * 4, Ag + (long)m * lda + k0 + ch * 8);
            cp16(dB + (m * GW + ch * 4) * 4, Bg + (long)m * ldb + k0 + ch * 8);
        }
        asm volatile("cp.async.commit_group;");
    };

    issue(0, 0);

    const int iters = K >> 5;
    for (int it = 0; it < iters; it++) {
        const int buf = it & 1;
        if (it + 1 < iters) {
            issue((it + 1) << 5, buf ^ 1);
            asm volatile("cp.async.wait_group 1;");
        } else {
            asm volatile("cp.async.wait_group 0;");
        }
        __syncthreads();

        const uint32_t* As = sm + buf * TILE_W;
        const uint32_t* Bs = sm + 2 * TILE_W + buf * TILE_W;

        #pragma unroll
        for (int kb = 0; kb < 2; kb++) {
            uint32_t a[4][4], bfr[4][2];
            #pragma unroll
            for (int mt = 0; mt < 4; mt++) {
                const int r = wm + mt * 16 + gid;
                a[mt][0] = As[(r    ) * GW + kb * 8 + tig    ];
                a[mt][1] = As[(r + 8) * GW + kb * 8 + tig    ];
                a[mt][2] = As[(r    ) * GW + kb * 8 + tig + 4];
                a[mt][3] = As[(r + 8) * GW + kb * 8 + tig + 4];
            }
            #pragma unroll
            for (int nt = 0; nt < 4; nt++) {
                const int c = wn + nt * 8 + gid;
                bfr[nt][0] = Bs[c * GW + kb * 8 + tig    ];
                bfr[nt][1] = Bs[c * GW + kb * 8 + tig + 4];
            }
            #pragma unroll
            for (int mt = 0; mt < 4; mt++)
                #pragma unroll
                for (int nt = 0; nt < 4; nt++)
                    mma_bf16(acc[mt][nt], a[mt], bfr[nt]);
        }
        __syncthreads();
    }

    // ---- epilogue ----
    #pragma unroll
    for (int mt = 0; mt < 4; mt++) {
        #pragma unroll
        for (int nt = 0; nt < 4; nt++) {
            #pragma unroll
            for (int half = 0; half < 2; half++) {
                const int r = m0 + wm + mt * 16 + gid + half * 8;
                const int c = n0 + wn + nt * 8 + tig * 2;
                float v0 = acc[mt][nt][half * 2 + 0];
                float v1 = acc[mt][nt][half * 2 + 1];
                if (bias) { v0 += bias[c]; v1 += bias[c + 1]; }
                if (GELU) {
                    v0 = 0.5f * v0 * (1.f + erff(v0 * 0.70710678118654752f));
                    v1 = 0.5f * v1 * (1.f + erff(v1 * 0.70710678118654752f));
                }
                if (res) {
                    v0 += res[(long)r * ldc + c];
                    v1 += res[(long)r * ldc + c + 1];
                }
                if (OUTBF) {
                    __nv_bfloat162* C = (__nv_bfloat162*)Cv;
                    C[((long)r * ldc + c) >> 1] =
                        __nv_bfloat162(__float2bfloat16(v0), __float2bfloat16(v1));
                } else {
                    float* C = (float*)Cv;
                    C[(long)r * ldc + c    ] = v0;
                    C[(long)r * ldc + c + 1] = v1;
                }
            }
        }
    }
}

// ---------------- fused flash attention (tf32, unchanged math) ----------------
#define KS_W 68
#define VS_W 72
#define PS_W 132
#define FLASH_SMEM ((128 * KS_W + 128 * VS_W + 128 * PS_W) * 4)

__global__ void __launch_bounds__(256, 1)
flash_attn_kernel(const float* __restrict__ qkv,
                  const float* __restrict__ rpe,
                  __nv_bfloat16* __restrict__ o)
{
    extern __shared__ uint32_t sh[];
    uint32_t* Ks = sh;
    uint32_t* Vs = Ks + 128 * KS_W;
    uint32_t* Ps = Vs + 128 * VS_W;

    const int bh = blockIdx.x;
    const int b  = bh / HEADS_, h = bh % HEADS_;
    const int i0 = blockIdx.y * 128;

    const int tid  = threadIdx.x;
    const int warp = tid >> 5;
    const int lane = tid & 31;
    const int gid  = lane >> 2;
    const int tig  = lane & 3;
    const int rw   = warp * 16;

    const long strideQ = 3 * DIM_;
    const float* Qp = qkv + (long)b * N_ * strideQ + h * HDIM_;
    const float* Kp = Qp + DIM_;
    const float* Vp = Qp + 2 * DIM_;

    uint32_t qa[8][4];
    {
        const float* q0 = Qp + (long)(i0 + rw + gid) * strideQ;
        const float* q1 = q0 + 8 * strideQ;
        #pragma unroll
        for (int kb = 0; kb < 8; kb++) {
            const int c = kb * 8 + tig;
            qa[kb][0] = f2tf32(q0[c]);
            qa[kb][1] = f2tf32(q1[c]);
            qa[kb][2] = f2tf32(q0[c + 4]);
            qa[kb][3] = f2tf32(q1[c + 4]);
        }
    }

    float oacc[8][4] = {};
    float m_lo = -1e30f, m_hi = -1e30f;
    float l_lo = 0.f, l_hi = 0.f;

    const float* rpe_row = rpe + (long)h * N_ * N_ + (long)(i0 + rw + gid) * N_;

    for (int j0 = 0; j0 < N_; j0 += 128) {
        __syncthreads();

        #pragma unroll
        for (int i = 0; i < 8; i++) {
            const int idx = tid + i * 256;
            const int j = idx >> 4;
            const int d = (idx & 15) * 4;
            const float4 kv = *(const float4*)(Kp + (long)(j0 + j) * strideQ + d);
            Ks[j * KS_W + d + 0] = f2tf32(kv.x);
            Ks[j * KS_W + d + 1] = f2tf32(kv.y);
            Ks[j * KS_W + d + 2] = f2tf32(kv.z);
            Ks[j * KS_W + d + 3] = f2tf32(kv.w);
            const float4 vv = *(const float4*)(Vp + (long)(j0 + j) * strideQ + d);
            Vs[j * VS_W + d + 0] = f2tf32(vv.x);
            Vs[j * VS_W + d + 1] = f2tf32(vv.y);
            Vs[j * VS_W + d + 2] = f2tf32(vv.z);
            Vs[j * VS_W + d + 3] = f2tf32(vv.w);
        }
        __syncthreads();

        float s[16][4] = {};
        #pragma unroll
        for (int kb = 0; kb < 8; kb++) {
            #pragma unroll
            for (int nt = 0; nt < 16; nt++) {
                uint32_t bf[2];
                bf[0] = Ks[(nt * 8 + gid) * KS_W + kb * 8 + tig];
                bf[1] = Ks[(nt * 8 + gid) * KS_W + kb * 8 + tig + 4];
                mma_tf32(s[nt], qa[kb], bf);
            }
        }

        float mx0 = -1e30f, mx1 = -1e30f;
        #pragma unroll
        for (int nt = 0; nt < 16; nt++) {
            const int c = j0 + nt * 8 + tig * 2;
            s[nt][0] = s[nt][0] * 0.125f + rpe_row[c];
            s[nt][1] = s[nt][1] * 0.125f + rpe_row[c + 1];
            s[nt][2] = s[nt][2] * 0.125f + rpe_row[8 * N_ + c];
            s[nt][3] = s[nt][3] * 0.125f + rpe_row[8 * N_ + c + 1];
            mx0 = fmaxf(mx0, fmaxf(s[nt][0], s[nt][1]));
            mx1 = fmaxf(mx1, fmaxf(s[nt][2], s[nt][3]));
        }
        mx0 = fmaxf(mx0, __shfl_xor_sync(~0u, mx0, 1));
        mx0 = fmaxf(mx0, __shfl_xor_sync(~0u, mx0, 2));
        mx1 = fmaxf(mx1, __shfl_xor_sync(~0u, mx1, 1));
        mx1 = fmaxf(mx1, __shfl_xor_sync(~0u, mx1, 2));

        const float mn0 = fmaxf(m_lo, mx0);
        const float mn1 = fmaxf(m_hi, mx1);
        const float f0 = __expf(m_lo - mn0);
        const float f1 = __expf(m_hi - mn1);
        m_lo = mn0; m_hi = mn1;

        float sum0 = 0.f, sum1 = 0.f;
        #pragma unroll
        for (int nt = 0; nt < 16; nt++) {
            const float p0 = __expf(s[nt][0] - m_lo);
            const float p1 = __expf(s[nt][1] - m_lo);
            const float p2 = __expf(s[nt][2] - m_hi);
            const float p3 = __expf(s[nt][3] - m_hi);
            sum0 += p0 + p1;
            sum1 += p2 + p3;
            const int c = nt * 8 + tig * 2;
            Ps[(c    ) * PS_W + rw + gid    ] = f2tf32(p0);
            Ps[(c + 1) * PS_W + rw + gid    ] = f2tf32(p1);
            Ps[(c    ) * PS_W + rw + gid + 8] = f2tf32(p2);
            Ps[(c + 1) * PS_W + rw + gid + 8] = f2tf32(p3);
        }
        sum0 += __shfl_xor_sync(~0u, sum0, 1);
        sum0 += __shfl_xor_sync(~0u, sum0, 2);
        sum1 += __shfl_xor_sync(~0u, sum1, 1);
        sum1 += __shfl_xor_sync(~0u, sum1, 2);
        l_lo = l_lo * f0 + sum0;
        l_hi = l_hi * f1 + sum1;

        #pragma unroll
        for (int nt = 0; nt < 8; nt++) {
            oacc[nt][0] *= f0; oacc[nt][1] *= f0;
            oacc[nt][2] *= f1; oacc[nt][3] *= f1;
        }
        __syncthreads();

        #pragma unroll
        for (int kb = 0; kb < 16; kb++) {
            uint32_t pa[4];
            pa[0] = Ps[(kb * 8 + tig    ) * PS_W + rw + gid    ];
            pa[1] = Ps[(kb * 8 + tig    ) * PS_W + rw + gid + 8];
            pa[2] = Ps[(kb * 8 + tig + 4) * PS_W + rw + gid    ];
            pa[3] = Ps[(kb * 8 + tig + 4) * PS_W + rw + gid + 8];
            #pragma unroll
            for (int nt = 0; nt < 8; nt++) {
                uint32_t bf[2];
                bf[0] = Vs[(kb * 8 + tig    ) * VS_W + nt * 8 + gid];
                bf[1] = Vs[(kb * 8 + tig + 4) * VS_W + nt * 8 + gid];
                mma_tf32(oacc[nt], pa, bf);
            }
        }
    }

    const float inv0 = 1.f / l_lo;
    const float inv1 = 1.f / l_hi;
    __nv_bfloat16* op0 = o + ((long)b * N_ + i0 + rw + gid) * DIM_ + h * HDIM_;
    __nv_bfloat16* op1 = op0 + 8 * DIM_;
    #pragma unroll
    for (int nt = 0; nt < 8; nt++) {
        const int c = nt * 8 + tig * 2;
        *(__nv_bfloat162*)(op0 + c) =
            __nv_bfloat162(__float2bfloat16(oacc[nt][0] * inv0),
                           __float2bfloat16(oacc[nt][1] * inv0));
        *(__nv_bfloat162*)(op1 + c) =
            __nv_bfloat162(__float2bfloat16(oacc[nt][2] * inv1),
                           __float2bfloat16(oacc[nt][3] * inv1));
    }
}

// ---------------- LayerNorm: one block per row, bf16 out ----------------
__global__ void ln_kernel(const float* __restrict__ x,
                          const float* __restrict__ g,
                          const float* __restrict__ b,
                          __nv_bfloat16* __restrict__ out)
{
    const int row = blockIdx.x;
    const float* xr = x + (long)row * DIM_;
    const int tid = threadIdx.x;
    __shared__ float sm[8];

    float v0 = xr[tid], v1 = xr[tid + 256], v2 = xr[tid + 512];
    float s = v0 + v1 + v2;
    #pragma unroll
    for (int o = 16; o; o >>= 1) s += __shfl_xor_sync(~0u, s, o);
    if ((tid & 31) == 0) sm[tid >> 5] = s;
    __syncthreads();
    s = sm[0];
    #pragma unroll
    for (int i = 1; i < 8; i++) s += sm[i];
    const float mu = s * (1.f / DIM_);
    __syncthreads();

    float d0 = v0 - mu, d1 = v1 - mu, d2 = v2 - mu;
    s = d0 * d0 + d1 * d1 + d2 * d2;
    #pragma unroll
    for (int o = 16; o; o >>= 1) s += __shfl_xor_sync(~0u, s, o);
    if ((tid & 31) == 0) sm[tid >> 5] = s;
    __syncthreads();
    s = sm[0];
    #pragma unroll
    for (int i = 1; i < 8; i++) s += sm[i];
    const float inv = rsqrtf(s * (1.f / DIM_) + 1e-5f);

    __nv_bfloat16* orow = out + (long)row * DIM_;
    orow[tid      ] = __float2bfloat16(d0 * inv * g[tid      ] + b[tid      ]);
    orow[tid + 256] = __float2bfloat16(d1 * inv * g[tid + 256] + b[tid + 256]);
    orow[tid + 512] = __float2bfloat16(d2 * inv * g[tid + 512] + b[tid + 512]);
}

// ---------------- host ----------------
template<typename T>
static T* symaddr(const T& sym)
{
    void* p = nullptr;
    cudaGetSymbolAddress(&p, sym);
    return (T*)p;
}

extern "C" void kernel_launch(void* const* d_in, const int* in_sizes, int n_in,
                              void* d_out, int out_size)
{
    const float* x      = (const float*)d_in[0];
    const float* rpe    = (const float*)d_in[1];
    const float* qkv_w  = (const float*)d_in[2];
    const float* proj_w = (const float*)d_in[3];
    const float* proj_b = (const float*)d_in[4];
    const float* ln1_g  = (const float*)d_in[5];
    const float* ln1_b  = (const float*)d_in[6];
    const float* ln2_g  = (const float*)d_in[7];
    const float* ln2_b  = (const float*)d_in[8];
    const float* fc1_w  = (const float*)d_in[9];
    const float* fc1_b  = (const float*)d_in[10];
    const float* fc2_w  = (const float*)d_in[11];
    const float* fc2_b  = (const float*)d_in[12];
    float* out = (float*)d_out;

    __nv_bfloat16* h_bf  = (__nv_bfloat16*)symaddr(g_h_bf);
    float*         qkv   = (float*)        symaddr(g_qkv);
    __nv_bfloat16* o_bf  = (__nv_bfloat16*)symaddr(g_o_bf);
    float*         x1    = (float*)        symaddr(g_x1);
    __nv_bfloat16* mlp   = (__nv_bfloat16*)symaddr(g_mlp);
    __nv_bfloat16* wqkv  = (__nv_bfloat16*)symaddr(g_wqkv);
    __nv_bfloat16* wproj = (__nv_bfloat16*)symaddr(g_wproj);
    __nv_bfloat16* wfc1  = (__nv_bfloat16*)symaddr(g_wfc1);
    __nv_bfloat16* wfc2  = (__nv_bfloat16*)symaddr(g_wfc2);

    cudaFuncSetAttribute(flash_attn_kernel,
                         cudaFuncAttributeMaxDynamicSharedMemorySize, FLASH_SMEM);

    dim3 blk(256);
    dim3 wblk(32, 8);

    // 0) weight prep (fp32 [K][N] -> bf16 [N][K])
    wprep<<<dim3(3 * DIM_ / 32, DIM_ / 32), wblk>>>(qkv_w,  wqkv,  DIM_, 3 * DIM_);
    wprep<<<dim3(DIM_ / 32,     DIM_ / 32), wblk>>>(proj_w, wproj, DIM_, DIM_);
    wprep<<<dim3(HIDDEN_ / 32,  DIM_ / 32), wblk>>>(fc1_w,  wfc1,  DIM_, HIDDEN_);
    wprep<<<dim3(DIM_ / 32, HIDDEN_ / 32),  wblk>>>(fc2_w,  wfc2,  HIDDEN_, DIM_);

    // 1) LN1 -> bf16
    ln_kernel<<<ROWS_, blk>>>(x, ln1_g, ln1_b, h_bf);

    // 2) QKV GEMM (bf16 in, fp32 out)
    bgemm<false, false><<<dim3(3 * DIM_ / 128, ROWS_ / 128), blk, BGEMM_SMEM>>>(
        h_bf, DIM_, wqkv, DIM_, qkv, 3 * DIM_, nullptr, nullptr, DIM_);

    // 3) fused attention -> bf16 o
    flash_attn_kernel<<<dim3(BH_, N_ / 128), blk, FLASH_SMEM>>>(qkv, rpe, o_bf);

    // 4) proj + bias + residual(x) -> fp32 x1
    bgemm<false, false><<<dim3(DIM_ / 128, ROWS_ / 128), blk, BGEMM_SMEM>>>(
        o_bf, DIM_, wproj, DIM_, x1, DIM_, proj_b, x, DIM_);

    // 5) LN2 -> bf16
    ln_kernel<<<ROWS_, blk>>>(x1, ln2_g, ln2_b, h_bf);

    // 6) FC1 + bias + gelu -> bf16 mlp
    bgemm<true, true><<<dim3(HIDDEN_ / 128, ROWS_ / 128), blk, BGEMM_SMEM>>>(
        h_bf, DIM_, wfc1, DIM_, mlp, HIDDEN_, fc1_b, nullptr, DIM_);

    // 7) FC2 + bias + residual(x1) -> out fp32
    bgemm<false, false><<<dim3(DIM_ / 128, ROWS_ / 128), blk, BGEMM_SMEM>>>(
        mlp, HIDDEN_, wfc2, HIDDEN_, out, DIM_, fc2_b, x1, HIDDEN_);
}

// round 5
// speedup vs baseline: 5.7884x; 1.1697x over previous
#include <cuda_runtime.h>
#include <cuda_bf16.h>
#include <math.h>
#include <stdint.h>

// ---------------- problem constants ----------------
#define B_      8
#define N_      1024
#define DIM_    768
#define HEADS_  12
#define HDIM_   64
#define HIDDEN_ 1536
#define ROWS_   (B_ * N_)            // 8192
#define BH_     (B_ * HEADS_)        // 96

// ---------------- scratch (device globals; no runtime alloc) ----------------
__device__ __nv_bfloat16 g_h_bf [ROWS_ * DIM_];      // LN output (bf16)
__device__ float         g_qkv  [ROWS_ * 3 * DIM_];  // fp32 (attention input)
__device__ __nv_bfloat16 g_vt   [(long)BH_ * HDIM_ * N_]; // V^T bf16 [bh][d][j]
__device__ __nv_bfloat16 g_o_bf [ROWS_ * DIM_];      // attention out (bf16)
__device__ float         g_x1   [ROWS_ * DIM_];      // residual stream fp32
__device__ __nv_bfloat16 g_mlp  [ROWS_ * HIDDEN_];   // gelu out (bf16)
// transposed bf16 weights [N][K]
__device__ __nv_bfloat16 g_wqkv [3 * DIM_ * DIM_];
__device__ __nv_bfloat16 g_wproj[DIM_ * DIM_];
__device__ __nv_bfloat16 g_wfc1 [HIDDEN_ * DIM_];
__device__ __nv_bfloat16 g_wfc2 [DIM_ * HIDDEN_];

// ---------------- helpers ----------------
__device__ __forceinline__ uint32_t f2tf32(float f)
{
    uint32_t u;
    asm("cvt.rna.tf32.f32 %0, %1;" : "=r"(u) : "f"(f));
    return u;
}

__device__ __forceinline__ uint32_t packbf2(float a, float b)
{
    __nv_bfloat162 t = __floats2bfloat162_rn(a, b);
    return *(uint32_t*)&t;
}

__device__ __forceinline__ void mma_tf32(float* c, const uint32_t* a, const uint32_t* b)
{
    asm volatile(
        "mma.sync.aligned.m16n8k8.row.col.f32.tf32.tf32.f32 "
        "{%0,%1,%2,%3}, {%4,%5,%6,%7}, {%8,%9}, {%0,%1,%2,%3};"
        : "+f"(c[0]), "+f"(c[1]), "+f"(c[2]), "+f"(c[3])
        : "r"(a[0]), "r"(a[1]), "r"(a[2]), "r"(a[3]),
          "r"(b[0]), "r"(b[1]));
}

__device__ __forceinline__ void mma_bf16(float* c, const uint32_t* a, const uint32_t* b)
{
    asm volatile(
        "mma.sync.aligned.m16n8k16.row.col.f32.bf16.bf16.f32 "
        "{%0,%1,%2,%3}, {%4,%5,%6,%7}, {%8,%9}, {%0,%1,%2,%3};"
        : "+f"(c[0]), "+f"(c[1]), "+f"(c[2]), "+f"(c[3])
        : "r"(a[0]), "r"(a[1]), "r"(a[2]), "r"(a[3]),
          "r"(b[0]), "r"(b[1]));
}

__device__ __forceinline__ void cp16(uint32_t dst, const void* src)
{
    asm volatile("cp.async.cg.shared.global [%0], [%1], 16;" :: "r"(dst), "l"(src));
}

// ---------------- weight prep: fp32 [K][N] -> bf16 [N][K] ----------------
__global__ void wprep(const float* __restrict__ w, __nv_bfloat16* __restrict__ wt,
                      int K, int N)
{
    __shared__ float t[32][33];
    const int n0 = blockIdx.x * 32, k0 = blockIdx.y * 32;
    const int tx = threadIdx.x, ty = threadIdx.y;   // 32 x 8
    #pragma unroll
    for (int i = 0; i < 32; i += 8)
        t[ty + i][tx] = w[(long)(k0 + ty + i) * N + n0 + tx];
    __syncthreads();
    #pragma unroll
    for (int i = 0; i < 32; i += 8)
        wt[(long)(n0 + ty + i) * K + k0 + tx] = __float2bfloat16(t[tx][ty + i]);
}

// ---------------- V transpose prep: qkv fp32 [token][c] -> vt bf16 [bh][d][j] ----------------
__global__ void __launch_bounds__(256)
vt_prep(const float* __restrict__ qkv, __nv_bfloat16* __restrict__ vt)
{
    __shared__ float t[64][65];
    const int bh = blockIdx.x;
    const int b = bh / HEADS_, h = bh % HEADS_;
    const int j0 = blockIdx.y * 64;
    const int tid = threadIdx.x;

    const float* Vp = qkv + (long)b * N_ * (3 * DIM_) + 2 * DIM_ + h * HDIM_;
    #pragma unroll
    for (int i = 0; i < 4; i++) {
        const int idx = tid + i * 256;
        const int r = idx >> 4;
        const int d = (idx & 15) * 4;
        const float4 v = *(const float4*)(Vp + (long)(j0 + r) * (3 * DIM_) + d);
        t[r][d] = v.x; t[r][d + 1] = v.y; t[r][d + 2] = v.z; t[r][d + 3] = v.w;
    }
    __syncthreads();

    uint32_t* out = (uint32_t*)(vt + ((long)bh * HDIM_) * N_ + j0);
    #pragma unroll
    for (int i = 0; i < 8; i++) {
        const int w = tid + i * 256;
        const int d = w >> 5;
        const int jw = w & 31;
        out[(long)d * (N_ / 2) + jw] = packbf2(t[2 * jw][d], t[2 * jw + 1][d]);
    }
}

// ---------------- bf16 pipelined GEMM (3-stage) ----------------
#define GW 20                        // smem words per 32-k row (16 data + 4 pad)
#define STG_W (2 * 128 * GW)         // words per stage (A + B)
#define BGEMM_SMEM (3 * STG_W * 4)   // 61440 B

template<bool GELU, bool OUTBF>
__global__ void __launch_bounds__(256)
bgemm(const __nv_bfloat16* __restrict__ A, int lda,
      const __nv_bfloat16* __restrict__ Bt, int ldb,
      void* __restrict__ Cv, int ldc,
      const float* __restrict__ bias,
      const float* __restrict__ res,
      int K)
{
    extern __shared__ uint32_t sm[];
    const uint32_t smem_base = (uint32_t)__cvta_generic_to_shared(sm);

    const int m0 = blockIdx.y * 128;
    const int n0 = blockIdx.x * 128;
    const int tid  = threadIdx.x;
    const int warp = tid >> 5;
    const int lane = tid & 31;
    const int gid  = lane >> 2;
    const int tig  = lane & 3;
    const int wm   = (warp >> 2) * 64;
    const int wn   = (warp & 3) * 32;

    const int lm = tid >> 2;
    const int ch = tid & 3;

    float acc[4][4][4] = {};

    const __nv_bfloat16* Ag = A + (long)m0 * lda;
    const __nv_bfloat16* Bg = Bt + (long)n0 * ldb;

    auto issue = [&](int k0, int buf) {
        const uint32_t dA = smem_base + (buf * STG_W) * 4;
        const uint32_t dB = dA + 128 * GW * 4;
        #pragma unroll
        for (int i = 0; i < 2; i++) {
            const int m = lm + i * 64;
            cp16(dA + (m * GW + ch * 4) * 4, Ag + (long)m * lda + k0 + ch * 8);
            cp16(dB + (m * GW + ch * 4) * 4, Bg + (long)m * ldb + k0 + ch * 8);
        }
        asm volatile("cp.async.commit_group;");
    };

    const int iters = K >> 5;
    issue(0, 0);
    issue(32, 1);

    for (int it = 0; it < iters; it++) {
        const int buf = it % 3;
        if (it + 2 < iters) {
            issue((it + 2) << 5, (it + 2) % 3);
            asm volatile("cp.async.wait_group 2;");
        } else if (it + 1 < iters) {
            asm volatile("cp.async.wait_group 1;");
        } else {
            asm volatile("cp.async.wait_group 0;");
        }
        __syncthreads();

        const uint32_t* As = sm + buf * STG_W;
        const uint32_t* Bs = As + 128 * GW;

        #pragma unroll
        for (int kb = 0; kb < 2; kb++) {
            uint32_t a[4][4], bfr[4][2];
            #pragma unroll
            for (int mt = 0; mt < 4; mt++) {
                const int r = wm + mt * 16 + gid;
                a[mt][0] = As[(r    ) * GW + kb * 8 + tig    ];
                a[mt][1] = As[(r + 8) * GW + kb * 8 + tig    ];
                a[mt][2] = As[(r    ) * GW + kb * 8 + tig + 4];
                a[mt][3] = As[(r + 8) * GW + kb * 8 + tig + 4];
            }
            #pragma unroll
            for (int nt = 0; nt < 4; nt++) {
                const int c = wn + nt * 8 + gid;
                bfr[nt][0] = Bs[c * GW + kb * 8 + tig    ];
                bfr[nt][1] = Bs[c * GW + kb * 8 + tig + 4];
            }
            #pragma unroll
            for (int mt = 0; mt < 4; mt++)
                #pragma unroll
                for (int nt = 0; nt < 4; nt++)
                    mma_bf16(acc[mt][nt], a[mt], bfr[nt]);
        }
        __syncthreads();
    }

    #pragma unroll
    for (int mt = 0; mt < 4; mt++) {
        #pragma unroll
        for (int nt = 0; nt < 4; nt++) {
            #pragma unroll
            for (int half = 0; half < 2; half++) {
                const int r = m0 + wm + mt * 16 + gid + half * 8;
                const int c = n0 + wn + nt * 8 + tig * 2;
                float v0 = acc[mt][nt][half * 2 + 0];
                float v1 = acc[mt][nt][half * 2 + 1];
                if (bias) { v0 += bias[c]; v1 += bias[c + 1]; }
                if (GELU) {
                    v0 = 0.5f * v0 * (1.f + erff(v0 * 0.70710678118654752f));
                    v1 = 0.5f * v1 * (1.f + erff(v1 * 0.70710678118654752f));
                }
                if (res) {
                    v0 += res[(long)r * ldc + c];
                    v1 += res[(long)r * ldc + c + 1];
                }
                if (OUTBF) {
                    __nv_bfloat162* C = (__nv_bfloat162*)Cv;
                    C[((long)r * ldc + c) >> 1] =
                        __nv_bfloat162(__float2bfloat16(v0), __float2bfloat16(v1));
                } else {
                    float* C = (float*)Cv;
                    C[(long)r * ldc + c    ] = v0;
                    C[(long)r * ldc + c + 1] = v1;
                }
            }
        }
    }
}

// ---------------- fused flash attention v2 ----------------
// One CTA per (bh, 128-row Q tile). j-tile = 64, double-buffered cp.async K/Vt.
// QK in tf32 (K raw fp32, HW-truncated); PV in bf16 with in-register P fragments.
#define KSW 68                           // fp32 words per K row (64 + 4 pad)
#define VTW 36                           // u32 words per Vt row (64 bf16 + 8 pad)
#define KS_TILE (64 * KSW)               // words per K buffer
#define VT_TILE (64 * VTW)               // words per Vt buffer
#define FLASH_SMEM ((2 * KS_TILE + 2 * VT_TILE) * 4)   // 53248 B

__global__ void __launch_bounds__(256)
flash_attn_kernel(const float* __restrict__ qkv,
                  const __nv_bfloat16* __restrict__ vt,
                  const float* __restrict__ rpe,
                  __nv_bfloat16* __restrict__ o)
{
    extern __shared__ uint32_t sh[];
    const uint32_t smem_base = (uint32_t)__cvta_generic_to_shared(sh);

    const int bh = blockIdx.x;
    const int b  = bh / HEADS_, h = bh % HEADS_;
    const int i0 = blockIdx.y * 128;

    const int tid  = threadIdx.x;
    const int warp = tid >> 5;
    const int lane = tid & 31;
    const int gid  = lane >> 2;
    const int tig  = lane & 3;
    const int rw   = warp * 16;

    const long strideQ = 3 * DIM_;
    const float* Qp = qkv + (long)b * N_ * strideQ + h * HDIM_;
    const float* Kp = Qp + DIM_;
    const __nv_bfloat16* Vtp = vt + (long)bh * HDIM_ * N_;

    // ---- Q fragments (tf32) ----
    uint32_t qa[8][4];
    {
        const float* q0 = Qp + (long)(i0 + rw + gid) * strideQ;
        const float* q1 = q0 + 8 * strideQ;
        #pragma unroll
        for (int kb = 0; kb < 8; kb++) {
            const int c = kb * 8 + tig;
            qa[kb][0] = f2tf32(q0[c]);
            qa[kb][1] = f2tf32(q1[c]);
            qa[kb][2] = f2tf32(q0[c + 4]);
            qa[kb][3] = f2tf32(q1[c + 4]);
        }
    }

    float oacc[8][4] = {};
    float m_lo = -1e30f, m_hi = -1e30f;
    float l_lo = 0.f, l_hi = 0.f;

    const float* rpe_row = rpe + (long)h * N_ * N_ + (long)(i0 + rw + gid) * N_;

    auto issueKV = [&](int j0, int buf) {
        const uint32_t dK = smem_base + (buf * KS_TILE) * 4;
        const uint32_t dV = smem_base + (2 * KS_TILE + buf * VT_TILE) * 4;
        #pragma unroll
        for (int i = 0; i < 4; i++) {           // K: 64 rows x 256B
            const int idx = tid + i * 256;
            const int r = idx >> 4, c = idx & 15;
            cp16(dK + r * (KSW * 4) + c * 16, Kp + (long)(j0 + r) * strideQ + c * 4);
        }
        #pragma unroll
        for (int i = 0; i < 2; i++) {           // Vt: 64 d-rows x 128B
            const int idx = tid + i * 256;
            const int d = idx >> 3, c = idx & 7;
            cp16(dV + d * (VTW * 4) + c * 16, Vtp + (long)d * N_ + j0 + c * 8);
        }
        asm volatile("cp.async.commit_group;");
    };

    issueKV(0, 0);

    for (int t = 0; t < 16; t++) {
        const int buf = t & 1;
        asm volatile("cp.async.wait_group 0;");
        __syncthreads();
        if (t + 1 < 16) issueKV((t + 1) * 64, buf ^ 1);

        const uint32_t* Ks = sh + buf * KS_TILE;
        const uint32_t* Vs = sh + 2 * KS_TILE + buf * VT_TILE;
        const int j0 = t * 64;

        // ---- S = Q @ K^T (16 x 64 per warp) ----
        float s[8][4] = {};
        #pragma unroll
        for (int kb = 0; kb < 8; kb++) {
            #pragma unroll
            for (int nt = 0; nt < 8; nt++) {
                uint32_t bf[2];
                bf[0] = Ks[(nt * 8 + gid) * KSW + kb * 8 + tig];
                bf[1] = Ks[(nt * 8 + gid) * KSW + kb * 8 + tig + 4];
                mma_tf32(s[nt], qa[kb], bf);
            }
        }

        // ---- scale + rpe, row max ----
        float mx0 = -1e30f, mx1 = -1e30f;
        #pragma unroll
        for (int nt = 0; nt < 8; nt++) {
            const int c = j0 + nt * 8 + tig * 2;
            s[nt][0] = s[nt][0] * 0.125f + rpe_row[c];
            s[nt][1] = s[nt][1] * 0.125f + rpe_row[c + 1];
            s[nt][2] = s[nt][2] * 0.125f + rpe_row[8 * N_ + c];
            s[nt][3] = s[nt][3] * 0.125f + rpe_row[8 * N_ + c + 1];
            mx0 = fmaxf(mx0, fmaxf(s[nt][0], s[nt][1]));
            mx1 = fmaxf(mx1, fmaxf(s[nt][2], s[nt][3]));
        }
        mx0 = fmaxf(mx0, __shfl_xor_sync(~0u, mx0, 1));
        mx0 = fmaxf(mx0, __shfl_xor_sync(~0u, mx0, 2));
        mx1 = fmaxf(mx1, __shfl_xor_sync(~0u, mx1, 1));
        mx1 = fmaxf(mx1, __shfl_xor_sync(~0u, mx1, 2));

        const float mn0 = fmaxf(m_lo, mx0);
        const float mn1 = fmaxf(m_hi, mx1);
        const float f0 = __expf(m_lo - mn0);
        const float f1 = __expf(m_hi - mn1);
        m_lo = mn0; m_hi = mn1;

        // ---- exp, sums, pack P fragments (bf16, in registers) ----
        uint32_t pf[8][2];
        float sum0 = 0.f, sum1 = 0.f;
        #pragma unroll
        for (int nt = 0; nt < 8; nt++) {
            const float p0 = __expf(s[nt][0] - m_lo);
            const float p1 = __expf(s[nt][1] - m_lo);
            const float p2 = __expf(s[nt][2] - m_hi);
            const float p3 = __expf(s[nt][3] - m_hi);
            sum0 += p0 + p1;
            sum1 += p2 + p3;
            pf[nt][0] = packbf2(p0, p1);   // row gid
            pf[nt][1] = packbf2(p2, p3);   // row gid+8
        }
        sum0 += __shfl_xor_sync(~0u, sum0, 1);
        sum0 += __shfl_xor_sync(~0u, sum0, 2);
        sum1 += __shfl_xor_sync(~0u, sum1, 1);
        sum1 += __shfl_xor_sync(~0u, sum1, 2);
        l_lo = l_lo * f0 + sum0;
        l_hi = l_hi * f1 + sum1;

        // ---- rescale O ----
        #pragma unroll
        for (int nt = 0; nt < 8; nt++) {
            oacc[nt][0] *= f0; oacc[nt][1] *= f0;
            oacc[nt][2] *= f1; oacc[nt][3] *= f1;
        }

        // ---- O += P @ V (bf16 m16n8k16, K = 64) ----
        #pragma unroll
        for (int kb = 0; kb < 4; kb++) {
            uint32_t a[4];
            a[0] = pf[2 * kb    ][0];
            a[1] = pf[2 * kb    ][1];
            a[2] = pf[2 * kb + 1][0];
            a[3] = pf[2 * kb + 1][1];
            #pragma unroll
            for (int nt = 0; nt < 8; nt++) {
                uint32_t bf[2];
                bf[0] = Vs[(nt * 8 + gid) * VTW + kb * 8 + tig];
                bf[1] = Vs[(nt * 8 + gid) * VTW + kb * 8 + tig + 4];
                mma_bf16(oacc[nt], a, bf);
            }
        }
        __syncthreads();
    }

    // ---- finalize ----
    const float inv0 = 1.f / l_lo;
    const float inv1 = 1.f / l_hi;
    __nv_bfloat16* op0 = o + ((long)b * N_ + i0 + rw + gid) * DIM_ + h * HDIM_;
    __nv_bfloat16* op1 = op0 + 8 * DIM_;
    #pragma unroll
    for (int nt = 0; nt < 8; nt++) {
        const int c = nt * 8 + tig * 2;
        *(__nv_bfloat162*)(op0 + c) =
            __nv_bfloat162(__float2bfloat16(oacc[nt][0] * inv0),
                           __float2bfloat16(oacc[nt][1] * inv0));
        *(__nv_bfloat162*)(op1 + c) =
            __nv_bfloat162(__float2bfloat16(oacc[nt][2] * inv1),
                           __float2bfloat16(oacc[nt][3] * inv1));
    }
}

// ---------------- LayerNorm: one block per row, bf16 out ----------------
__global__ void ln_kernel(const float* __restrict__ x,
                          const float* __restrict__ g,
                          const float* __restrict__ b,
                          __nv_bfloat16* __restrict__ out)
{
    const int row = blockIdx.x;
    const float* xr = x + (long)row * DIM_;
    const int tid = threadIdx.x;
    __shared__ float sm[8];

    float v0 = xr[tid], v1 = xr[tid + 256], v2 = xr[tid + 512];
    float s = v0 + v1 + v2;
    #pragma unroll
    for (int o = 16; o; o >>= 1) s += __shfl_xor_sync(~0u, s, o);
    if ((tid & 31) == 0) sm[tid >> 5] = s;
    __syncthreads();
    s = sm[0];
    #pragma unroll
    for (int i = 1; i < 8; i++) s += sm[i];
    const float mu = s * (1.f / DIM_);
    __syncthreads();

    float d0 = v0 - mu, d1 = v1 - mu, d2 = v2 - mu;
    s = d0 * d0 + d1 * d1 + d2 * d2;
    #pragma unroll
    for (int o = 16; o; o >>= 1) s += __shfl_xor_sync(~0u, s, o);
    if ((tid & 31) == 0) sm[tid >> 5] = s;
    __syncthreads();
    s = sm[0];
    #pragma unroll
    for (int i = 1; i < 8; i++) s += sm[i];
    const float inv = rsqrtf(s * (1.f / DIM_) + 1e-5f);

    __nv_bfloat16* orow = out + (long)row * DIM_;
    orow[tid      ] = __float2bfloat16(d0 * inv * g[tid      ] + b[tid      ]);
    orow[tid + 256] = __float2bfloat16(d1 * inv * g[tid + 256] + b[tid + 256]);
    orow[tid + 512] = __float2bfloat16(d2 * inv * g[tid + 512] + b[tid + 512]);
}

// ---------------- host ----------------
template<typename T>
static T* symaddr(const T& sym)
{
    void* p = nullptr;
    cudaGetSymbolAddress(&p, sym);
    return (T*)p;
}

extern "C" void kernel_launch(void* const* d_in, const int* in_sizes, int n_in,
                              void* d_out, int out_size)
{
    const float* x      = (const float*)d_in[0];
    const float* rpe    = (const float*)d_in[1];
    const float* qkv_w  = (const float*)d_in[2];
    const float* proj_w = (const float*)d_in[3];
    const float* proj_b = (const float*)d_in[4];
    const float* ln1_g  = (const float*)d_in[5];
    const float* ln1_b  = (const float*)d_in[6];
    const float* ln2_g  = (const float*)d_in[7];
    const float* ln2_b  = (const float*)d_in[8];
    const float* fc1_w  = (const float*)d_in[9];
    const float* fc1_b  = (const float*)d_in[10];
    const float* fc2_w  = (const float*)d_in[11];
    const float* fc2_b  = (const float*)d_in[12];
    float* out = (float*)d_out;

    __nv_bfloat16* h_bf  = (__nv_bfloat16*)symaddr(g_h_bf);
    float*         qkv   = (float*)        symaddr(g_qkv);
    __nv_bfloat16* vt    = (__nv_bfloat16*)symaddr(g_vt);
    __nv_bfloat16* o_bf  = (__nv_bfloat16*)symaddr(g_o_bf);
    float*         x1    = (float*)        symaddr(g_x1);
    __nv_bfloat16* mlp   = (__nv_bfloat16*)symaddr(g_mlp);
    __nv_bfloat16* wqkv  = (__nv_bfloat16*)symaddr(g_wqkv);
    __nv_bfloat16* wproj = (__nv_bfloat16*)symaddr(g_wproj);
    __nv_bfloat16* wfc1  = (__nv_bfloat16*)symaddr(g_wfc1);
    __nv_bfloat16* wfc2  = (__nv_bfloat16*)symaddr(g_wfc2);

    cudaFuncSetAttribute(flash_attn_kernel,
                         cudaFuncAttributeMaxDynamicSharedMemorySize, FLASH_SMEM);
    cudaFuncSetAttribute(bgemm<false, false>,
                         cudaFuncAttributeMaxDynamicSharedMemorySize, BGEMM_SMEM);
    cudaFuncSetAttribute(bgemm<true, true>,
                         cudaFuncAttributeMaxDynamicSharedMemorySize, BGEMM_SMEM);

    dim3 blk(256);
    dim3 wblk(32, 8);

    // 0) weight prep
    wprep<<<dim3(3 * DIM_ / 32, DIM_ / 32), wblk>>>(qkv_w,  wqkv,  DIM_, 3 * DIM_);
    wprep<<<dim3(DIM_ / 32,     DIM_ / 32), wblk>>>(proj_w, wproj, DIM_, DIM_);
    wprep<<<dim3(HIDDEN_ / 32,  DIM_ / 32), wblk>>>(fc1_w,  wfc1,  DIM_, HIDDEN_);
    wprep<<<dim3(DIM_ / 32, HIDDEN_ / 32),  wblk>>>(fc2_w,  wfc2,  HIDDEN_, DIM_);

    // 1) LN1 -> bf16
    ln_kernel<<<ROWS_, blk>>>(x, ln1_g, ln1_b, h_bf);

    // 2) QKV GEMM (bf16 in, fp32 out)
    bgemm<false, false><<<dim3(3 * DIM_ / 128, ROWS_ / 128), blk, BGEMM_SMEM>>>(
        h_bf, DIM_, wqkv, DIM_, qkv, 3 * DIM_, nullptr, nullptr, DIM_);

    // 2b) V^T bf16 prep
    vt_prep<<<dim3(BH_, N_ / 64), blk>>>(qkv, vt);

    // 3) fused attention -> bf16 o
    flash_attn_kernel<<<dim3(BH_, N_ / 128), blk, FLASH_SMEM>>>(qkv, vt, rpe, o_bf);

    // 4) proj + bias + residual(x) -> fp32 x1
    bgemm<false, false><<<dim3(DIM_ / 128, ROWS_ / 128), blk, BGEMM_SMEM>>>(
        o_bf, DIM_, wproj, DIM_, x1, DIM_, proj_b, x, DIM_);

    // 5) LN2 -> bf16
    ln_kernel<<<ROWS_, blk>>>(x1, ln2_g, ln2_b, h_bf);

    // 6) FC1 + bias + gelu -> bf16 mlp
    bgemm<true, true><<<dim3(HIDDEN_ / 128, ROWS_ / 128), blk, BGEMM_SMEM>>>(
        h_bf, DIM_, wfc1, DIM_, mlp, HIDDEN_, fc1_b, nullptr, DIM_);

    // 7) FC2 + bias + residual(x1) -> out fp32
    bgemm<false, false><<<dim3(DIM_ / 128, ROWS_ / 128), blk, BGEMM_SMEM>>>(
        mlp, HIDDEN_, wfc2, HIDDEN_, out, DIM_, fc2_b, x1, HIDDEN_);
}

// round 6
// speedup vs baseline: 5.8433x; 1.0095x over previous
#include <cuda_runtime.h>
#include <cuda_bf16.h>
#include <math.h>
#include <stdint.h>

// ---------------- problem constants ----------------
#define B_      8
#define N_      1024
#define DIM_    768
#define HEADS_  12
#define HDIM_   64
#define HIDDEN_ 1536
#define ROWS_   (B_ * N_)            // 8192
#define BH_     (B_ * HEADS_)        // 96

// ---------------- scratch (device globals; no runtime alloc) ----------------
__device__ __nv_bfloat16 g_h_bf [ROWS_ * DIM_];
__device__ float         g_qkv  [ROWS_ * 3 * DIM_];
__device__ __nv_bfloat16 g_vt   [(long)BH_ * HDIM_ * N_]; // V^T bf16 [bh'][d][j]
__device__ __nv_bfloat16 g_o_bf [ROWS_ * DIM_];
__device__ float         g_x1   [ROWS_ * DIM_];
__device__ __nv_bfloat16 g_mlp  [ROWS_ * HIDDEN_];
__device__ __nv_bfloat16 g_wqkv [3 * DIM_ * DIM_];
__device__ __nv_bfloat16 g_wproj[DIM_ * DIM_];
__device__ __nv_bfloat16 g_wfc1 [HIDDEN_ * DIM_];
__device__ __nv_bfloat16 g_wfc2 [DIM_ * HIDDEN_];

// ---------------- helpers ----------------
__device__ __forceinline__ uint32_t f2tf32(float f)
{
    uint32_t u;
    asm("cvt.rna.tf32.f32 %0, %1;" : "=r"(u) : "f"(f));
    return u;
}

__device__ __forceinline__ uint32_t packbf2(float a, float b)
{
    __nv_bfloat162 t = __floats2bfloat162_rn(a, b);
    return *(uint32_t*)&t;
}

__device__ __forceinline__ void mma_tf32(float* c, const uint32_t* a, const uint32_t* b)
{
    asm volatile(
        "mma.sync.aligned.m16n8k8.row.col.f32.tf32.tf32.f32 "
        "{%0,%1,%2,%3}, {%4,%5,%6,%7}, {%8,%9}, {%0,%1,%2,%3};"
        : "+f"(c[0]), "+f"(c[1]), "+f"(c[2]), "+f"(c[3])
        : "r"(a[0]), "r"(a[1]), "r"(a[2]), "r"(a[3]),
          "r"(b[0]), "r"(b[1]));
}

__device__ __forceinline__ void mma_bf16(float* c, const uint32_t* a, const uint32_t* b)
{
    asm volatile(
        "mma.sync.aligned.m16n8k16.row.col.f32.bf16.bf16.f32 "
        "{%0,%1,%2,%3}, {%4,%5,%6,%7}, {%8,%9}, {%0,%1,%2,%3};"
        : "+f"(c[0]), "+f"(c[1]), "+f"(c[2]), "+f"(c[3])
        : "r"(a[0]), "r"(a[1]), "r"(a[2]), "r"(a[3]),
          "r"(b[0]), "r"(b[1]));
}

__device__ __forceinline__ void cp16(uint32_t dst, const void* src)
{
    asm volatile("cp.async.cg.shared.global [%0], [%1], 16;" :: "r"(dst), "l"(src));
}

__device__ __forceinline__ void ldsm_x4(uint32_t& r0, uint32_t& r1, uint32_t& r2,
                                        uint32_t& r3, uint32_t addr)
{
    asm volatile("ldmatrix.sync.aligned.m8n8.x4.shared.b16 {%0,%1,%2,%3}, [%4];"
                 : "=r"(r0), "=r"(r1), "=r"(r2), "=r"(r3) : "r"(addr));
}

__device__ __forceinline__ void ldsm_x2(uint32_t& r0, uint32_t& r1, uint32_t addr)
{
    asm volatile("ldmatrix.sync.aligned.m8n8.x2.shared.b16 {%0,%1}, [%2];"
                 : "=r"(r0), "=r"(r1) : "r"(addr));
}

// ---------------- weight prep: fp32 [K][N] -> bf16 [N][K] ----------------
__global__ void wprep(const float* __restrict__ w, __nv_bfloat16* __restrict__ wt,
                      int K, int N)
{
    __shared__ float t[32][33];
    const int n0 = blockIdx.x * 32, k0 = blockIdx.y * 32;
    const int tx = threadIdx.x, ty = threadIdx.y;   // 32 x 8
    #pragma unroll
    for (int i = 0; i < 32; i += 8)
        t[ty + i][tx] = w[(long)(k0 + ty + i) * N + n0 + tx];
    __syncthreads();
    #pragma unroll
    for (int i = 0; i < 32; i += 8)
        wt[(long)(n0 + ty + i) * K + k0 + tx] = __float2bfloat16(t[tx][ty + i]);
}

// ---------------- V transpose prep (bh' = h*B_ + b ordering) ----------------
__global__ void __launch_bounds__(256)
vt_prep(const float* __restrict__ qkv, __nv_bfloat16* __restrict__ vt)
{
    __shared__ float t[64][65];
    const int bh = blockIdx.x;
    const int h = bh / B_, b = bh % B_;
    const int j0 = blockIdx.y * 64;
    const int tid = threadIdx.x;

    const float* Vp = qkv + (long)b * N_ * (3 * DIM_) + 2 * DIM_ + h * HDIM_;
    #pragma unroll
    for (int i = 0; i < 4; i++) {
        const int idx = tid + i * 256;
        const int r = idx >> 4;
        const int d = (idx & 15) * 4;
        const float4 v = *(const float4*)(Vp + (long)(j0 + r) * (3 * DIM_) + d);
        t[r][d] = v.x; t[r][d + 1] = v.y; t[r][d + 2] = v.z; t[r][d + 3] = v.w;
    }
    __syncthreads();

    uint32_t* out = (uint32_t*)(vt + ((long)bh * HDIM_) * N_ + j0);
    #pragma unroll
    for (int i = 0; i < 8; i++) {
        const int w = tid + i * 256;
        const int d = w >> 5;
        const int jw = w & 31;
        out[(long)d * (N_ / 2) + jw] = packbf2(t[2 * jw][d], t[2 * jw + 1][d]);
    }
}

// ---------------- bf16 pipelined GEMM (3-stage, ldmatrix fragments) ----------------
#define GW 20                        // smem words per 32-k row (16 data + 4 pad)
#define STG_W (2 * 128 * GW)
#define BGEMM_SMEM (3 * STG_W * 4)   // 61440 B

template<bool GELU, bool OUTBF>
__global__ void __launch_bounds__(256)
bgemm(const __nv_bfloat16* __restrict__ A, int lda,
      const __nv_bfloat16* __restrict__ Bt, int ldb,
      void* __restrict__ Cv, int ldc,
      const float* __restrict__ bias,
      const float* __restrict__ res,
      int K)
{
    extern __shared__ uint32_t sm[];
    const uint32_t smem_base = (uint32_t)__cvta_generic_to_shared(sm);

    const int m0 = blockIdx.y * 128;
    const int n0 = blockIdx.x * 128;
    const int tid  = threadIdx.x;
    const int warp = tid >> 5;
    const int lane = tid & 31;
    const int gid  = lane >> 2;
    const int tig  = lane & 3;
    const int wm   = (warp >> 2) * 64;
    const int wn   = (warp & 3) * 32;

    const int lm = tid >> 2;
    const int ch = tid & 3;

    float acc[4][4][4] = {};

    const __nv_bfloat16* Ag = A + (long)m0 * lda;
    const __nv_bfloat16* Bg = Bt + (long)n0 * ldb;

    auto issue = [&](int k0, int buf) {
        const uint32_t dA = smem_base + (buf * STG_W) * 4;
        const uint32_t dB = dA + 128 * GW * 4;
        #pragma unroll
        for (int i = 0; i < 2; i++) {
            const int m = lm + i * 64;
            cp16(dA + (m * GW + ch * 4) * 4, Ag + (long)m * lda + k0 + ch * 8);
            cp16(dB + (m * GW + ch * 4) * 4, Bg + (long)m * ldb + k0 + ch * 8);
        }
        asm volatile("cp.async.commit_group;");
    };

    const int iters = K >> 5;
    issue(0, 0);
    issue(32, 1);

    // per-thread ldmatrix source addresses (byte offsets inside a stage)
    const int a_row = wm + (lane & 15);          // + mt*16
    const int a_half = (lane >> 4) * 16;         // 0 or 16 bytes (k0-7 / k8-15)
    const int b_row = wn + (lane & 7);           // + nt*8
    const int b_half = ((lane >> 3) & 1) * 16;

    for (int it = 0; it < iters; it++) {
        const int buf = it % 3;
        if (it + 2 < iters) {
            issue((it + 2) << 5, (it + 2) % 3);
            asm volatile("cp.async.wait_group 2;");
        } else if (it + 1 < iters) {
            asm volatile("cp.async.wait_group 1;");
        } else {
            asm volatile("cp.async.wait_group 0;");
        }
        __syncthreads();

        const uint32_t sA = smem_base + (buf * STG_W) * 4;
        const uint32_t sB = sA + 128 * GW * 4;

        #pragma unroll
        for (int kb = 0; kb < 2; kb++) {
            uint32_t a[4][4], bfr[4][2];
            #pragma unroll
            for (int mt = 0; mt < 4; mt++)
                ldsm_x4(a[mt][0], a[mt][1], a[mt][2], a[mt][3],
                        sA + (a_row + mt * 16) * (GW * 4) + kb * 32 + a_half);
            #pragma unroll
            for (int nt = 0; nt < 4; nt++)
                ldsm_x2(bfr[nt][0], bfr[nt][1],
                        sB + (b_row + nt * 8) * (GW * 4) + kb * 32 + b_half);
            #pragma unroll
            for (int mt = 0; mt < 4; mt++)
                #pragma unroll
                for (int nt = 0; nt < 4; nt++)
                    mma_bf16(acc[mt][nt], a[mt], bfr[nt]);
        }
        __syncthreads();
    }

    #pragma unroll
    for (int mt = 0; mt < 4; mt++) {
        #pragma unroll
        for (int nt = 0; nt < 4; nt++) {
            #pragma unroll
            for (int half = 0; half < 2; half++) {
                const int r = m0 + wm + mt * 16 + gid + half * 8;
                const int c = n0 + wn + nt * 8 + tig * 2;
                float v0 = acc[mt][nt][half * 2 + 0];
                float v1 = acc[mt][nt][half * 2 + 1];
                if (bias) { v0 += bias[c]; v1 += bias[c + 1]; }
                if (GELU) {
                    v0 = 0.5f * v0 * (1.f + erff(v0 * 0.70710678118654752f));
                    v1 = 0.5f * v1 * (1.f + erff(v1 * 0.70710678118654752f));
                }
                if (res) {
                    v0 += res[(long)r * ldc + c];
                    v1 += res[(long)r * ldc + c + 1];
                }
                if (OUTBF) {
                    __nv_bfloat162* C = (__nv_bfloat162*)Cv;
                    C[((long)r * ldc + c) >> 1] =
                        __nv_bfloat162(__float2bfloat16(v0), __float2bfloat16(v1));
                } else {
                    float* C = (float*)Cv;
                    C[(long)r * ldc + c    ] = v0;
                    C[(long)r * ldc + c + 1] = v1;
                }
            }
        }
    }
}

// ---------------- fused flash attention v2 (b-fastest grid for rpe reuse) ----------------
#define KSW 68
#define VTW 36
#define KS_TILE (64 * KSW)
#define VT_TILE (64 * VTW)
#define FLASH_SMEM ((2 * KS_TILE + 2 * VT_TILE) * 4)   // 53248 B

__global__ void __launch_bounds__(256)
flash_attn_kernel(const float* __restrict__ qkv,
                  const __nv_bfloat16* __restrict__ vt,
                  const float* __restrict__ rpe,
                  __nv_bfloat16* __restrict__ o)
{
    extern __shared__ uint32_t sh[];
    const uint32_t smem_base = (uint32_t)__cvta_generic_to_shared(sh);

    const int bh = blockIdx.x;
    const int h = bh / B_, b = bh % B_;   // b fastest: 8 consecutive CTAs share rpe
    const int i0 = blockIdx.y * 128;

    const int tid  = threadIdx.x;
    const int warp = tid >> 5;
    const int lane = tid & 31;
    const int gid  = lane >> 2;
    const int tig  = lane & 3;
    const int rw   = warp * 16;

    const long strideQ = 3 * DIM_;
    const float* Qp = qkv + (long)b * N_ * strideQ + h * HDIM_;
    const float* Kp = Qp + DIM_;
    const __nv_bfloat16* Vtp = vt + (long)bh * HDIM_ * N_;

    uint32_t qa[8][4];
    {
        const float* q0 = Qp + (long)(i0 + rw + gid) * strideQ;
        const float* q1 = q0 + 8 * strideQ;
        #pragma unroll
        for (int kb = 0; kb < 8; kb++) {
            const int c = kb * 8 + tig;
            qa[kb][0] = f2tf32(q0[c]);
            qa[kb][1] = f2tf32(q1[c]);
            qa[kb][2] = f2tf32(q0[c + 4]);
            qa[kb][3] = f2tf32(q1[c + 4]);
        }
    }

    float oacc[8][4] = {};
    float m_lo = -1e30f, m_hi = -1e30f;
    float l_lo = 0.f, l_hi = 0.f;

    const float* rpe_row = rpe + (long)h * N_ * N_ + (long)(i0 + rw + gid) * N_;

    auto issueKV = [&](int j0, int buf) {
        const uint32_t dK = smem_base + (buf * KS_TILE) * 4;
        const uint32_t dV = smem_base + (2 * KS_TILE + buf * VT_TILE) * 4;
        #pragma unroll
        for (int i = 0; i < 4; i++) {
            const int idx = tid + i * 256;
            const int r = idx >> 4, c = idx & 15;
            cp16(dK + r * (KSW * 4) + c * 16, Kp + (long)(j0 + r) * strideQ + c * 4);
        }
        #pragma unroll
        for (int i = 0; i < 2; i++) {
            const int idx = tid + i * 256;
            const int d = idx >> 3, c = idx & 7;
            cp16(dV + d * (VTW * 4) + c * 16, Vtp + (long)d * N_ + j0 + c * 8);
        }
        asm volatile("cp.async.commit_group;");
    };

    issueKV(0, 0);

    for (int t = 0; t < 16; t++) {
        const int buf = t & 1;
        asm volatile("cp.async.wait_group 0;");
        __syncthreads();
        if (t + 1 < 16) issueKV((t + 1) * 64, buf ^ 1);

        const uint32_t* Ks = sh + buf * KS_TILE;
        const uint32_t* Vs = sh + 2 * KS_TILE + buf * VT_TILE;
        const int j0 = t * 64;

        float s[8][4] = {};
        #pragma unroll
        for (int kb = 0; kb < 8; kb++) {
            #pragma unroll
            for (int nt = 0; nt < 8; nt++) {
                uint32_t bf[2];
                bf[0] = Ks[(nt * 8 + gid) * KSW + kb * 8 + tig];
                bf[1] = Ks[(nt * 8 + gid) * KSW + kb * 8 + tig + 4];
                mma_tf32(s[nt], qa[kb], bf);
            }
        }

        float mx0 = -1e30f, mx1 = -1e30f;
        #pragma unroll
        for (int nt = 0; nt < 8; nt++) {
            const int c = j0 + nt * 8 + tig * 2;
            s[nt][0] = s[nt][0] * 0.125f + rpe_row[c];
            s[nt][1] = s[nt][1] * 0.125f + rpe_row[c + 1];
            s[nt][2] = s[nt][2] * 0.125f + rpe_row[8 * N_ + c];
            s[nt][3] = s[nt][3] * 0.125f + rpe_row[8 * N_ + c + 1];
            mx0 = fmaxf(mx0, fmaxf(s[nt][0], s[nt][1]));
            mx1 = fmaxf(mx1, fmaxf(s[nt][2], s[nt][3]));
        }
        mx0 = fmaxf(mx0, __shfl_xor_sync(~0u, mx0, 1));
        mx0 = fmaxf(mx0, __shfl_xor_sync(~0u, mx0, 2));
        mx1 = fmaxf(mx1, __shfl_xor_sync(~0u, mx1, 1));
        mx1 = fmaxf(mx1, __shfl_xor_sync(~0u, mx1, 2));

        const float mn0 = fmaxf(m_lo, mx0);
        const float mn1 = fmaxf(m_hi, mx1);
        const float f0 = __expf(m_lo - mn0);
        const float f1 = __expf(m_hi - mn1);
        m_lo = mn0; m_hi = mn1;

        uint32_t pf[8][2];
        float sum0 = 0.f, sum1 = 0.f;
        #pragma unroll
        for (int nt = 0; nt < 8; nt++) {
            const float p0 = __expf(s[nt][0] - m_lo);
            const float p1 = __expf(s[nt][1] - m_lo);
            const float p2 = __expf(s[nt][2] - m_hi);
            const float p3 = __expf(s[nt][3] - m_hi);
            sum0 += p0 + p1;
            sum1 += p2 + p3;
            pf[nt][0] = packbf2(p0, p1);
            pf[nt][1] = packbf2(p2, p3);
        }
        sum0 += __shfl_xor_sync(~0u, sum0, 1);
        sum0 += __shfl_xor_sync(~0u, sum0, 2);
        sum1 += __shfl_xor_sync(~0u, sum1, 1);
        sum1 += __shfl_xor_sync(~0u, sum1, 2);
        l_lo = l_lo * f0 + sum0;
        l_hi = l_hi * f1 + sum1;

        #pragma unroll
        for (int nt = 0; nt < 8; nt++) {
            oacc[nt][0] *= f0; oacc[nt][1] *= f0;
            oacc[nt][2] *= f1; oacc[nt][3] *= f1;
        }

        #pragma unroll
        for (int kb = 0; kb < 4; kb++) {
            uint32_t a[4];
            a[0] = pf[2 * kb    ][0];
            a[1] = pf[2 * kb    ][1];
            a[2] = pf[2 * kb + 1][0];
            a[3] = pf[2 * kb + 1][1];
            #pragma unroll
            for (int nt = 0; nt < 8; nt++) {
                uint32_t bf[2];
                bf[0] = Vs[(nt * 8 + gid) * VTW + kb * 8 + tig];
                bf[1] = Vs[(nt * 8 + gid) * VTW + kb * 8 + tig + 4];
                mma_bf16(oacc[nt], a, bf);
            }
        }
        __syncthreads();
    }

    const float inv0 = 1.f / l_lo;
    const float inv1 = 1.f / l_hi;
    __nv_bfloat16* op0 = o + ((long)b * N_ + i0 + rw + gid) * DIM_ + h * HDIM_;
    __nv_bfloat16* op1 = op0 + 8 * DIM_;
    #pragma unroll
    for (int nt = 0; nt < 8; nt++) {
        const int c = nt * 8 + tig * 2;
        *(__nv_bfloat162*)(op0 + c) =
            __nv_bfloat162(__float2bfloat16(oacc[nt][0] * inv0),
                           __float2bfloat16(oacc[nt][1] * inv0));
        *(__nv_bfloat162*)(op1 + c) =
            __nv_bfloat162(__float2bfloat16(oacc[nt][2] * inv1),
                           __float2bfloat16(oacc[nt][3] * inv1));
    }
}

// ---------------- LayerNorm ----------------
__global__ void ln_kernel(const float* __restrict__ x,
                          const float* __restrict__ g,
                          const float* __restrict__ b,
                          __nv_bfloat16* __restrict__ out)
{
    const int row = blockIdx.x;
    const float* xr = x + (long)row * DIM_;
    const int tid = threadIdx.x;
    __shared__ float sm[8];

    float v0 = xr[tid], v1 = xr[tid + 256], v2 = xr[tid + 512];
    float s = v0 + v1 + v2;
    #pragma unroll
    for (int o = 16; o; o >>= 1) s += __shfl_xor_sync(~0u, s, o);
    if ((tid & 31) == 0) sm[tid >> 5] = s;
    __syncthreads();
    s = sm[0];
    #pragma unroll
    for (int i = 1; i < 8; i++) s += sm[i];
    const float mu = s * (1.f / DIM_);
    __syncthreads();

    float d0 = v0 - mu, d1 = v1 - mu, d2 = v2 - mu;
    s = d0 * d0 + d1 * d1 + d2 * d2;
    #pragma unroll
    for (int o = 16; o; o >>= 1) s += __shfl_xor_sync(~0u, s, o);
    if ((tid & 31) == 0) sm[tid >> 5] = s;
    __syncthreads();
    s = sm[0];
    #pragma unroll
    for (int i = 1; i < 8; i++) s += sm[i];
    const float inv = rsqrtf(s * (1.f / DIM_) + 1e-5f);

    __nv_bfloat16* orow = out + (long)row * DIM_;
    orow[tid      ] = __float2bfloat16(d0 * inv * g[tid      ] + b[tid      ]);
    orow[tid + 256] = __float2bfloat16(d1 * inv * g[tid + 256] + b[tid + 256]);
    orow[tid + 512] = __float2bfloat16(d2 * inv * g[tid + 512] + b[tid + 512]);
}

// ---------------- host ----------------
template<typename T>
static T* symaddr(const T& sym)
{
    void* p = nullptr;
    cudaGetSymbolAddress(&p, sym);
    return (T*)p;
}

extern "C" void kernel_launch(void* const* d_in, const int* in_sizes, int n_in,
                              void* d_out, int out_size)
{
    const float* x      = (const float*)d_in[0];
    const float* rpe    = (const float*)d_in[1];
    const float* qkv_w  = (const float*)d_in[2];
    const float* proj_w = (const float*)d_in[3];
    const float* proj_b = (const float*)d_in[4];
    const float* ln1_g  = (const float*)d_in[5];
    const float* ln1_b  = (const float*)d_in[6];
    const float* ln2_g  = (const float*)d_in[7];
    const float* ln2_b  = (const float*)d_in[8];
    const float* fc1_w  = (const float*)d_in[9];
    const float* fc1_b  = (const float*)d_in[10];
    const float* fc2_w  = (const float*)d_in[11];
    const float* fc2_b  = (const float*)d_in[12];
    float* out = (float*)d_out;

    __nv_bfloat16* h_bf  = (__nv_bfloat16*)symaddr(g_h_bf);
    float*         qkv   = (float*)        symaddr(g_qkv);
    __nv_bfloat16* vt    = (__nv_bfloat16*)symaddr(g_vt);
    __nv_bfloat16* o_bf  = (__nv_bfloat16*)symaddr(g_o_bf);
    float*         x1    = (float*)        symaddr(g_x1);
    __nv_bfloat16* mlp   = (__nv_bfloat16*)symaddr(g_mlp);
    __nv_bfloat16* wqkv  = (__nv_bfloat16*)symaddr(g_wqkv);
    __nv_bfloat16* wproj = (__nv_bfloat16*)symaddr(g_wproj);
    __nv_bfloat16* wfc1  = (__nv_bfloat16*)symaddr(g_wfc1);
    __nv_bfloat16* wfc2  = (__nv_bfloat16*)symaddr(g_wfc2);

    cudaFuncSetAttribute(flash_attn_kernel,
                         cudaFuncAttributeMaxDynamicSharedMemorySize, FLASH_SMEM);
    cudaFuncSetAttribute(bgemm<false, false>,
                         cudaFuncAttributeMaxDynamicSharedMemorySize, BGEMM_SMEM);
    cudaFuncSetAttribute(bgemm<true, true>,
                         cudaFuncAttributeMaxDynamicSharedMemorySize, BGEMM_SMEM);

    dim3 blk(256);
    dim3 wblk(32, 8);

    // 0) weight prep
    wprep<<<dim3(3 * DIM_ / 32, DIM_ / 32), wblk>>>(qkv_w,  wqkv,  DIM_, 3 * DIM_);
    wprep<<<dim3(DIM_ / 32,     DIM_ / 32), wblk>>>(proj_w, wproj, DIM_, DIM_);
    wprep<<<dim3(HIDDEN_ / 32,  DIM_ / 32), wblk>>>(fc1_w,  wfc1,  DIM_, HIDDEN_);
    wprep<<<dim3(DIM_ / 32, HIDDEN_ / 32),  wblk>>>(fc2_w,  wfc2,  HIDDEN_, DIM_);

    // 1) LN1 -> bf16
    ln_kernel<<<ROWS_, blk>>>(x, ln1_g, ln1_b, h_bf);

    // 2) QKV GEMM
    bgemm<false, false><<<dim3(3 * DIM_ / 128, ROWS_ / 128), blk, BGEMM_SMEM>>>(
        h_bf, DIM_, wqkv, DIM_, qkv, 3 * DIM_, nullptr, nullptr, DIM_);

    // 2b) V^T bf16 prep
    vt_prep<<<dim3(BH_, N_ / 64), blk>>>(qkv, vt);

    // 3) fused attention -> bf16 o
    flash_attn_kernel<<<dim3(BH_, N_ / 128), blk, FLASH_SMEM>>>(qkv, vt, rpe, o_bf);

    // 4) proj + bias + residual(x) -> fp32 x1
    bgemm<false, false><<<dim3(DIM_ / 128, ROWS_ / 128), blk, BGEMM_SMEM>>>(
        o_bf, DIM_, wproj, DIM_, x1, DIM_, proj_b, x, DIM_);

    // 5) LN2 -> bf16
    ln_kernel<<<ROWS_, blk>>>(x1, ln2_g, ln2_b, h_bf);

    // 6) FC1 + bias + gelu -> bf16 mlp
    bgemm<true, true><<<dim3(HIDDEN_ / 128, ROWS_ / 128), blk, BGEMM_SMEM>>>(
        h_bf, DIM_, wfc1, DIM_, mlp, HIDDEN_, fc1_b, nullptr, DIM_);

    // 7) FC2 + bias + residual(x1) -> out fp32
    bgemm<false, false><<<dim3(DIM_ / 128, ROWS_ / 128), blk, BGEMM_SMEM>>>(
        mlp, HIDDEN_, wfc2, HIDDEN_, out, DIM_, fc2_b, x1, HIDDEN_);
}

// round 8
// speedup vs baseline: 6.0529x; 1.0359x over previous
#include <cuda_runtime.h>
#include <cuda_bf16.h>
#include <math.h>
#include <stdint.h>

// ---------------- problem constants ----------------
#define B_      8
#define N_      1024
#define DIM_    768
#define HEADS_  12
#define HDIM_   64
#define HIDDEN_ 1536
#define ROWS_   (B_ * N_)            // 8192
#define BH_     (B_ * HEADS_)        // 96

// ---------------- scratch ----------------
__device__ __nv_bfloat16 g_h_bf [ROWS_ * DIM_];
__device__ float         g_qkv  [ROWS_ * 3 * DIM_];
__device__ __nv_bfloat16 g_vt   [(long)BH_ * HDIM_ * N_];
__device__ __nv_bfloat16 g_o_bf [ROWS_ * DIM_];
__device__ float         g_x1   [ROWS_ * DIM_];
__device__ __nv_bfloat16 g_mlp  [ROWS_ * HIDDEN_];
__device__ __nv_bfloat16 g_wqkv [3 * DIM_ * DIM_];
__device__ __nv_bfloat16 g_wproj[DIM_ * DIM_];
__device__ __nv_bfloat16 g_wfc1 [HIDDEN_ * DIM_];
__device__ __nv_bfloat16 g_wfc2 [DIM_ * HIDDEN_];

// ---------------- helpers ----------------
__device__ __forceinline__ uint32_t f2tf32(float f)
{
    uint32_t u;
    asm("cvt.rna.tf32.f32 %0, %1;" : "=r"(u) : "f"(f));
    return u;
}

__device__ __forceinline__ uint32_t packbf2(float a, float b)
{
    __nv_bfloat162 t = __floats2bfloat162_rn(a, b);
    return *(uint32_t*)&t;
}

__device__ __forceinline__ void mma_tf32(float* c, const uint32_t* a, const uint32_t* b)
{
    asm volatile(
        "mma.sync.aligned.m16n8k8.row.col.f32.tf32.tf32.f32 "
        "{%0,%1,%2,%3}, {%4,%5,%6,%7}, {%8,%9}, {%0,%1,%2,%3};"
        : "+f"(c[0]), "+f"(c[1]), "+f"(c[2]), "+f"(c[3])
        : "r"(a[0]), "r"(a[1]), "r"(a[2]), "r"(a[3]),
          "r"(b[0]), "r"(b[1]));
}

__device__ __forceinline__ void mma_bf16(float* c, const uint32_t* a, const uint32_t* b)
{
    asm volatile(
        "mma.sync.aligned.m16n8k16.row.col.f32.bf16.bf16.f32 "
        "{%0,%1,%2,%3}, {%4,%5,%6,%7}, {%8,%9}, {%0,%1,%2,%3};"
        : "+f"(c[0]), "+f"(c[1]), "+f"(c[2]), "+f"(c[3])
        : "r"(a[0]), "r"(a[1]), "r"(a[2]), "r"(a[3]),
          "r"(b[0]), "r"(b[1]));
}

__device__ __forceinline__ void cp16(uint32_t dst, const void* src)
{
    asm volatile("cp.async.cg.shared.global [%0], [%1], 16;" :: "r"(dst), "l"(src));
}

__device__ __forceinline__ void ldsm_x4(uint32_t& r0, uint32_t& r1, uint32_t& r2,
                                        uint32_t& r3, uint32_t addr)
{
    asm volatile("ldmatrix.sync.aligned.m8n8.x4.shared.b16 {%0,%1,%2,%3}, [%4];"
                 : "=r"(r0), "=r"(r1), "=r"(r2), "=r"(r3) : "r"(addr));
}

__device__ __forceinline__ void ldsm_x2(uint32_t& r0, uint32_t& r1, uint32_t addr)
{
    asm volatile("ldmatrix.sync.aligned.m8n8.x2.shared.b16 {%0,%1}, [%2];"
                 : "=r"(r0), "=r"(r1) : "r"(addr));
}

// ---------------- weight prep: fp32 [K][N] -> bf16 [N][K] ----------------
__global__ void wprep(const float* __restrict__ w, __nv_bfloat16* __restrict__ wt,
                      int K, int N)
{
    __shared__ float t[32][33];
    const int n0 = blockIdx.x * 32, k0 = blockIdx.y * 32;
    const int tx = threadIdx.x, ty = threadIdx.y;
    #pragma unroll
    for (int i = 0; i < 32; i += 8)
        t[ty + i][tx] = w[(long)(k0 + ty + i) * N + n0 + tx];
    __syncthreads();
    #pragma unroll
    for (int i = 0; i < 32; i += 8)
        wt[(long)(n0 + ty + i) * K + k0 + tx] = __float2bfloat16(t[tx][ty + i]);
}

// ---------------- V transpose prep ----------------
__global__ void __launch_bounds__(256)
vt_prep(const float* __restrict__ qkv, __nv_bfloat16* __restrict__ vt)
{
    __shared__ float t[64][65];
    const int bh = blockIdx.x;
    const int h = bh / B_, b = bh % B_;
    const int j0 = blockIdx.y * 64;
    const int tid = threadIdx.x;

    const float* Vp = qkv + (long)b * N_ * (3 * DIM_) + 2 * DIM_ + h * HDIM_;
    #pragma unroll
    for (int i = 0; i < 4; i++) {
        const int idx = tid + i * 256;
        const int r = idx >> 4;
        const int d = (idx & 15) * 4;
        const float4 v = *(const float4*)(Vp + (long)(j0 + r) * (3 * DIM_) + d);
        t[r][d] = v.x; t[r][d + 1] = v.y; t[r][d + 2] = v.z; t[r][d + 3] = v.w;
    }
    __syncthreads();

    uint32_t* out = (uint32_t*)(vt + ((long)bh * HDIM_) * N_ + j0);
    #pragma unroll
    for (int i = 0; i < 8; i++) {
        const int w = tid + i * 256;
        const int d = w >> 5;
        const int jw = w & 31;
        out[(long)d * (N_ / 2) + jw] = packbf2(t[2 * jw][d], t[2 * jw + 1][d]);
    }
}

// ---------------- shared epilogue ----------------
template<bool GELU, bool OUTBF>
__device__ __forceinline__ void epi_write(void* Cv, int ldc,
                                          const float* bias, const float* res,
                                          int r, int c, float v0, float v1)
{
    if (bias) { v0 += bias[c]; v1 += bias[c + 1]; }
    if (GELU) {
        v0 = 0.5f * v0 * (1.f + erff(v0 * 0.70710678118654752f));
        v1 = 0.5f * v1 * (1.f + erff(v1 * 0.70710678118654752f));
    }
    if (res) {
        v0 += res[(long)r * ldc + c];
        v1 += res[(long)r * ldc + c + 1];
    }
    if (OUTBF) {
        __nv_bfloat162* C = (__nv_bfloat162*)Cv;
        C[((long)r * ldc + c) >> 1] =
            __nv_bfloat162(__float2bfloat16(v0), __float2bfloat16(v1));
    } else {
        float* C = (float*)Cv;
        C[(long)r * ldc + c    ] = v0;
        C[(long)r * ldc + c + 1] = v1;
    }
}

// ---------------- bf16 GEMM, 128x128 tile, 3-stage (R6-proven) ----------------
#define GW 20
#define STG_W (2 * 128 * GW)
#define BGEMM_SMEM (3 * STG_W * 4)   // 61440 B

template<bool GELU, bool OUTBF>
__global__ void __launch_bounds__(256)
bgemm(const __nv_bfloat16* __restrict__ A, int lda,
      const __nv_bfloat16* __restrict__ Bt, int ldb,
      void* __restrict__ Cv, int ldc,
      const float* __restrict__ bias,
      const float* __restrict__ res,
      int K)
{
    extern __shared__ uint32_t sm[];
    const uint32_t smem_base = (uint32_t)__cvta_generic_to_shared(sm);

    const int m0 = blockIdx.y * 128;
    const int n0 = blockIdx.x * 128;
    const int tid  = threadIdx.x;
    const int warp = tid >> 5;
    const int lane = tid & 31;
    const int gid  = lane >> 2;
    const int tig  = lane & 3;
    const int wm   = (warp >> 2) * 64;
    const int wn   = (warp & 3) * 32;

    const int lm = tid >> 2;
    const int ch = tid & 3;

    float acc[4][4][4] = {};

    const __nv_bfloat16* Ag = A + (long)m0 * lda;
    const __nv_bfloat16* Bg = Bt + (long)n0 * ldb;

    auto issue = [&](int k0, int buf) {
        const uint32_t dA = smem_base + (buf * STG_W) * 4;
        const uint32_t dB = dA + 128 * GW * 4;
        #pragma unroll
        for (int i = 0; i < 2; i++) {
            const int m = lm + i * 64;
            cp16(dA + (m * GW + ch * 4) * 4, Ag + (long)m * lda + k0 + ch * 8);
            cp16(dB + (m * GW + ch * 4) * 4, Bg + (long)m * ldb + k0 + ch * 8);
        }
        asm volatile("cp.async.commit_group;");
    };

    const int iters = K >> 5;
    issue(0, 0);
    issue(32, 1);

    const int a_row = wm + (lane & 15);
    const int a_half = (lane >> 4) * 16;
    const int b_row = wn + (lane & 7);
    const int b_half = ((lane >> 3) & 1) * 16;

    for (int it = 0; it < iters; it++) {
        const int buf = it % 3;
        if (it + 2 < iters) {
            issue((it + 2) << 5, (it + 2) % 3);
            asm volatile("cp.async.wait_group 2;");
        } else if (it + 1 < iters) {
            asm volatile("cp.async.wait_group 1;");
        } else {
            asm volatile("cp.async.wait_group 0;");
        }
        __syncthreads();

        const uint32_t sA = smem_base + (buf * STG_W) * 4;
        const uint32_t sB = sA + 128 * GW * 4;

        #pragma unroll
        for (int kb = 0; kb < 2; kb++) {
            uint32_t a[4][4], bfr[4][2];
            #pragma unroll
            for (int mt = 0; mt < 4; mt++)
                ldsm_x4(a[mt][0], a[mt][1], a[mt][2], a[mt][3],
                        sA + (a_row + mt * 16) * (GW * 4) + kb * 32 + a_half);
            #pragma unroll
            for (int nt = 0; nt < 4; nt++)
                ldsm_x2(bfr[nt][0], bfr[nt][1],
                        sB + (b_row + nt * 8) * (GW * 4) + kb * 32 + b_half);
            #pragma unroll
            for (int mt = 0; mt < 4; mt++)
                #pragma unroll
                for (int nt = 0; nt < 4; nt++)
                    mma_bf16(acc[mt][nt], a[mt], bfr[nt]);
        }
        __syncthreads();
    }

    #pragma unroll
    for (int mt = 0; mt < 4; mt++)
        #pragma unroll
        for (int nt = 0; nt < 4; nt++)
            #pragma unroll
            for (int half = 0; half < 2; half++)
                epi_write<GELU, OUTBF>(Cv, ldc, bias, res,
                    m0 + wm + mt * 16 + gid + half * 8,
                    n0 + wn + nt * 8 + tig * 2,
                    acc[mt][nt][half * 2 + 0], acc[mt][nt][half * 2 + 1]);
}

// ---------------- bf16 GEMM, 128x256 tile, 4-stage, 1 sync/iter ----------------
#define WGW 20
#define WSTG_W ((128 + 256) * WGW)          // 7680 words / stage
#define WGEMM_SMEM (4 * WSTG_W * 4)         // 122880 B

template<bool GELU, bool OUTBF>
__global__ void __launch_bounds__(256)
bgemm_wide(const __nv_bfloat16* __restrict__ A, int lda,
           const __nv_bfloat16* __restrict__ Bt, int ldb,
           void* __restrict__ Cv, int ldc,
           const float* __restrict__ bias,
           const float* __restrict__ res,
           int K)
{
    extern __shared__ uint32_t sm[];
    const uint32_t smem_base = (uint32_t)__cvta_generic_to_shared(sm);

    const int m0 = blockIdx.y * 128;
    const int n0 = blockIdx.x * 256;
    const int tid  = threadIdx.x;
    const int warp = tid >> 5;
    const int lane = tid & 31;
    const int gid  = lane >> 2;
    const int tig  = lane & 3;
    const int wm   = (warp >> 2) * 64;     // 2 warp-rows
    const int wn   = (warp & 3) * 64;      // 4 warp-cols, 64 wide each

    const int lm = tid >> 2;
    const int ch = tid & 3;

    float acc[4][8][4] = {};

    const __nv_bfloat16* Ag = A + (long)m0 * lda;
    const __nv_bfloat16* Bg = Bt + (long)n0 * ldb;

    auto issue = [&](int k0, int buf) {
        const uint32_t dA = smem_base + (buf * WSTG_W) * 4;
        const uint32_t dB = dA + 128 * WGW * 4;
        #pragma unroll
        for (int i = 0; i < 2; i++) {
            const int m = lm + i * 64;
            cp16(dA + (m * WGW + ch * 4) * 4, Ag + (long)m * lda + k0 + ch * 8);
        }
        #pragma unroll
        for (int i = 0; i < 4; i++) {
            const int m = lm + i * 64;
            cp16(dB + (m * WGW + ch * 4) * 4, Bg + (long)m * ldb + k0 + ch * 8);
        }
        asm volatile("cp.async.commit_group;");
    };

    const int iters = K >> 5;
    issue(0, 0);
    if (iters > 1) issue(32, 1);

    const int a_row = wm + (lane & 15);
    const int a_half = (lane >> 4) * 16;
    const int b_row = wn + (lane & 7);
    const int b_half = ((lane >> 3) & 1) * 16;

    for (int it = 0; it < iters; it++) {
        const int buf = it & 3;
        if (it + 2 < iters) {
            issue((it + 2) << 5, (it + 2) & 3);
            asm volatile("cp.async.wait_group 2;");
        } else if (it + 1 < iters) {
            asm volatile("cp.async.wait_group 1;");
        } else {
            asm volatile("cp.async.wait_group 0;");
        }
        __syncthreads();   // single sync: prefetch targets (it+2)&3/(it+3)&3, never (it)&3

        const uint32_t sA = smem_base + (buf * WSTG_W) * 4;
        const uint32_t sB = sA + 128 * WGW * 4;

        #pragma unroll
        for (int kb = 0; kb < 2; kb++) {
            uint32_t a[4][4], bfr[8][2];
            #pragma unroll
            for (int mt = 0; mt < 4; mt++)
                ldsm_x4(a[mt][0], a[mt][1], a[mt][2], a[mt][3],
                        sA + (a_row + mt * 16) * (WGW * 4) + kb * 32 + a_half);
            #pragma unroll
            for (int nt = 0; nt < 8; nt++)
                ldsm_x2(bfr[nt][0], bfr[nt][1],
                        sB + (b_row + nt * 8) * (WGW * 4) + kb * 32 + b_half);
            #pragma unroll
            for (int mt = 0; mt < 4; mt++)
                #pragma unroll
                for (int nt = 0; nt < 8; nt++)
                    mma_bf16(acc[mt][nt], a[mt], bfr[nt]);
        }
    }

    #pragma unroll
    for (int mt = 0; mt < 4; mt++)
        #pragma unroll
        for (int nt = 0; nt < 8; nt++)
            #pragma unroll
            for (int half = 0; half < 2; half++)
                epi_write<GELU, OUTBF>(Cv, ldc, bias, res,
                    m0 + wm + mt * 16 + gid + half * 8,
                    n0 + wn + nt * 8 + tig * 2,
                    acc[mt][nt][half * 2 + 0], acc[mt][nt][half * 2 + 1]);
}

// ---------------- fused flash attention (R6, unchanged) ----------------
#define KSW 68
#define VTW 36
#define KS_TILE (64 * KSW)
#define VT_TILE (64 * VTW)
#define FLASH_SMEM ((2 * KS_TILE + 2 * VT_TILE) * 4)

__global__ void __launch_bounds__(256)
flash_attn_kernel(const float* __restrict__ qkv,
                  const __nv_bfloat16* __restrict__ vt,
                  const float* __restrict__ rpe,
                  __nv_bfloat16* __restrict__ o)
{
    extern __shared__ uint32_t sh[];
    const uint32_t smem_base = (uint32_t)__cvta_generic_to_shared(sh);

    const int bh = blockIdx.x;
    const int h = bh / B_, b = bh % B_;
    const int i0 = blockIdx.y * 128;

    const int tid  = threadIdx.x;
    const int warp = tid >> 5;
    const int lane = tid & 31;
    const int gid  = lane >> 2;
    const int tig  = lane & 3;
    const int rw   = warp * 16;

    const long strideQ = 3 * DIM_;
    const float* Qp = qkv + (long)b * N_ * strideQ + h * HDIM_;
    const float* Kp = Qp + DIM_;
    const __nv_bfloat16* Vtp = vt + (long)bh * HDIM_ * N_;

    uint32_t qa[8][4];
    {
        const float* q0 = Qp + (long)(i0 + rw + gid) * strideQ;
        const float* q1 = q0 + 8 * strideQ;
        #pragma unroll
        for (int kb = 0; kb < 8; kb++) {
            const int c = kb * 8 + tig;
            qa[kb][0] = f2tf32(q0[c]);
            qa[kb][1] = f2tf32(q1[c]);
            qa[kb][2] = f2tf32(q0[c + 4]);
            qa[kb][3] = f2tf32(q1[c + 4]);
        }
    }

    float oacc[8][4] = {};
    float m_lo = -1e30f, m_hi = -1e30f;
    float l_lo = 0.f, l_hi = 0.f;

    const float* rpe_row = rpe + (long)h * N_ * N_ + (long)(i0 + rw + gid) * N_;

    auto issueKV = [&](int j0, int buf) {
        const uint32_t dK = smem_base + (buf * KS_TILE) * 4;
        const uint32_t dV = smem_base + (2 * KS_TILE + buf * VT_TILE) * 4;
        #pragma unroll
        for (int i = 0; i < 4; i++) {
            const int idx = tid + i * 256;
            const int r = idx >> 4, c = idx & 15;
            cp16(dK + r * (KSW * 4) + c * 16, Kp + (long)(j0 + r) * strideQ + c * 4);
        }
        #pragma unroll
        for (int i = 0; i < 2; i++) {
            const int idx = tid + i * 256;
            const int d = idx >> 3, c = idx & 7;
            cp16(dV + d * (VTW * 4) + c * 16, Vtp + (long)d * N_ + j0 + c * 8);
        }
        asm volatile("cp.async.commit_group;");
    };

    issueKV(0, 0);

    for (int t = 0; t < 16; t++) {
        const int buf = t & 1;
        asm volatile("cp.async.wait_group 0;");
        __syncthreads();
        if (t + 1 < 16) issueKV((t + 1) * 64, buf ^ 1);

        const uint32_t* Ks = sh + buf * KS_TILE;
        const uint32_t* Vs = sh + 2 * KS_TILE + buf * VT_TILE;
        const int j0 = t * 64;

        float s[8][4] = {};
        #pragma unroll
        for (int kb = 0; kb < 8; kb++) {
            #pragma unroll
            for (int nt = 0; nt < 8; nt++) {
                uint32_t bf[2];
                bf[0] = Ks[(nt * 8 + gid) * KSW + kb * 8 + tig];
                bf[1] = Ks[(nt * 8 + gid) * KSW + kb * 8 + tig + 4];
                mma_tf32(s[nt], qa[kb], bf);
            }
        }

        float mx0 = -1e30f, mx1 = -1e30f;
        #pragma unroll
        for (int nt = 0; nt < 8; nt++) {
            const int c = j0 + nt * 8 + tig * 2;
            s[nt][0] = s[nt][0] * 0.125f + rpe_row[c];
            s[nt][1] = s[nt][1] * 0.125f + rpe_row[c + 1];
            s[nt][2] = s[nt][2] * 0.125f + rpe_row[8 * N_ + c];
            s[nt][3] = s[nt][3] * 0.125f + rpe_row[8 * N_ + c + 1];
            mx0 = fmaxf(mx0, fmaxf(s[nt][0], s[nt][1]));
            mx1 = fmaxf(mx1, fmaxf(s[nt][2], s[nt][3]));
        }
        mx0 = fmaxf(mx0, __shfl_xor_sync(~0u, mx0, 1));
        mx0 = fmaxf(mx0, __shfl_xor_sync(~0u, mx0, 2));
        mx1 = fmaxf(mx1, __shfl_xor_sync(~0u, mx1, 1));
        mx1 = fmaxf(mx1, __shfl_xor_sync(~0u, mx1, 2));

        const float mn0 = fmaxf(m_lo, mx0);
        const float mn1 = fmaxf(m_hi, mx1);
        const float f0 = __expf(m_lo - mn0);
        const float f1 = __expf(m_hi - mn1);
        m_lo = mn0; m_hi = mn1;

        uint32_t pf[8][2];
        float sum0 = 0.f, sum1 = 0.f;
        #pragma unroll
        for (int nt = 0; nt < 8; nt++) {
            const float p0 = __expf(s[nt][0] - m_lo);
            const float p1 = __expf(s[nt][1] - m_lo);
            const float p2 = __expf(s[nt][2] - m_hi);
            const float p3 = __expf(s[nt][3] - m_hi);
            sum0 += p0 + p1;
            sum1 += p2 + p3;
            pf[nt][0] = packbf2(p0, p1);
            pf[nt][1] = packbf2(p2, p3);
        }
        sum0 += __shfl_xor_sync(~0u, sum0, 1);
        sum0 += __shfl_xor_sync(~0u, sum0, 2);
        sum1 += __shfl_xor_sync(~0u, sum1, 1);
        sum1 += __shfl_xor_sync(~0u, sum1, 2);
        l_lo = l_lo * f0 + sum0;
        l_hi = l_hi * f1 + sum1;

        #pragma unroll
        for (int nt = 0; nt < 8; nt++) {
            oacc[nt][0] *= f0; oacc[nt][1] *= f0;
            oacc[nt][2] *= f1; oacc[nt][3] *= f1;
        }

        #pragma unroll
        for (int kb = 0; kb < 4; kb++) {
            uint32_t a[4];
            a[0] = pf[2 * kb    ][0];
            a[1] = pf[2 * kb    ][1];
            a[2] = pf[2 * kb + 1][0];
            a[3] = pf[2 * kb + 1][1];
            #pragma unroll
            for (int nt = 0; nt < 8; nt++) {
                uint32_t bf[2];
                bf[0] = Vs[(nt * 8 + gid) * VTW + kb * 8 + tig];
                bf[1] = Vs[(nt * 8 + gid) * VTW + kb * 8 + tig + 4];
                mma_bf16(oacc[nt], a, bf);
            }
        }
        __syncthreads();
    }

    const float inv0 = 1.f / l_lo;
    const float inv1 = 1.f / l_hi;
    __nv_bfloat16* op0 = o + ((long)b * N_ + i0 + rw + gid) * DIM_ + h * HDIM_;
    __nv_bfloat16* op1 = op0 + 8 * DIM_;
    #pragma unroll
    for (int nt = 0; nt < 8; nt++) {
        const int c = nt * 8 + tig * 2;
        *(__nv_bfloat162*)(op0 + c) =
            __nv_bfloat162(__float2bfloat16(oacc[nt][0] * inv0),
                           __float2bfloat16(oacc[nt][1] * inv0));
        *(__nv_bfloat162*)(op1 + c) =
            __nv_bfloat162(__float2bfloat16(oacc[nt][2] * inv1),
                           __float2bfloat16(oacc[nt][3] * inv1));
    }
}

// ---------------- LayerNorm ----------------
__global__ void ln_kernel(const float* __restrict__ x,
                          const float* __restrict__ g,
                          const float* __restrict__ b,
                          __nv_bfloat16* __restrict__ out)
{
    const int row = blockIdx.x;
    const float* xr = x + (long)row * DIM_;
    const int tid = threadIdx.x;
    __shared__ float sm[8];

    float v0 = xr[tid], v1 = xr[tid + 256], v2 = xr[tid + 512];
    float s = v0 + v1 + v2;
    #pragma unroll
    for (int o = 16; o; o >>= 1) s += __shfl_xor_sync(~0u, s, o);
    if ((tid & 31) == 0) sm[tid >> 5] = s;
    __syncthreads();
    s = sm[0];
    #pragma unroll
    for (int i = 1; i < 8; i++) s += sm[i];
    const float mu = s * (1.f / DIM_);
    __syncthreads();

    float d0 = v0 - mu, d1 = v1 - mu, d2 = v2 - mu;
    s = d0 * d0 + d1 * d1 + d2 * d2;
    #pragma unroll
    for (int o = 16; o; o >>= 1) s += __shfl_xor_sync(~0u, s, o);
    if ((tid & 31) == 0) sm[tid >> 5] = s;
    __syncthreads();
    s = sm[0];
    #pragma unroll
    for (int i = 1; i < 8; i++) s += sm[i];
    const float inv = rsqrtf(s * (1.f / DIM_) + 1e-5f);

    __nv_bfloat16* orow = out + (long)row * DIM_;
    orow[tid      ] = __float2bfloat16(d0 * inv * g[tid      ] + b[tid      ]);
    orow[tid + 256] = __float2bfloat16(d1 * inv * g[tid + 256] + b[tid + 256]);
    orow[tid + 512] = __float2bfloat16(d2 * inv * g[tid + 512] + b[tid + 512]);
}

// ---------------- host ----------------
template<typename T>
static T* symaddr(const T& sym)
{
    void* p = nullptr;
    cudaGetSymbolAddress(&p, sym);
    return (T*)p;
}

extern "C" void kernel_launch(void* const* d_in, const int* in_sizes, int n_in,
                              void* d_out, int out_size)
{
    const float* x      = (const float*)d_in[0];
    const float* rpe    = (const float*)d_in[1];
    const float* qkv_w  = (const float*)d_in[2];
    const float* proj_w = (const float*)d_in[3];
    const float* proj_b = (const float*)d_in[4];
    const float* ln1_g  = (const float*)d_in[5];
    const float* ln1_b  = (const float*)d_in[6];
    const float* ln2_g  = (const float*)d_in[7];
    const float* ln2_b  = (const float*)d_in[8];
    const float* fc1_w  = (const float*)d_in[9];
    const float* fc1_b  = (const float*)d_in[10];
    const float* fc2_w  = (const float*)d_in[11];
    const float* fc2_b  = (const float*)d_in[12];
    float* out = (float*)d_out;

    __nv_bfloat16* h_bf  = (__nv_bfloat16*)symaddr(g_h_bf);
    float*         qkv   = (float*)        symaddr(g_qkv);
    __nv_bfloat16* vt    = (__nv_bfloat16*)symaddr(g_vt);
    __nv_bfloat16* o_bf  = (__nv_bfloat16*)symaddr(g_o_bf);
    float*         x1    = (float*)        symaddr(g_x1);
    __nv_bfloat16* mlp   = (__nv_bfloat16*)symaddr(g_mlp);
    __nv_bfloat16* wqkv  = (__nv_bfloat16*)symaddr(g_wqkv);
    __nv_bfloat16* wproj = (__nv_bfloat16*)symaddr(g_wproj);
    __nv_bfloat16* wfc1  = (__nv_bfloat16*)symaddr(g_wfc1);
    __nv_bfloat16* wfc2  = (__nv_bfloat16*)symaddr(g_wfc2);

    cudaFuncSetAttribute(flash_attn_kernel,
                         cudaFuncAttributeMaxDynamicSharedMemorySize, FLASH_SMEM);
    cudaFuncSetAttribute(bgemm<false, false>,
                         cudaFuncAttributeMaxDynamicSharedMemorySize, BGEMM_SMEM);
    cudaFuncSetAttribute(bgemm_wide<false, false>,
                         cudaFuncAttributeMaxDynamicSharedMemorySize, WGEMM_SMEM);
    cudaFuncSetAttribute(bgemm_wide<true, true>,
                         cudaFuncAttributeMaxDynamicSharedMemorySize, WGEMM_SMEM);

    dim3 wblk(32, 8);

    // 0) weight prep
    wprep<<<dim3(3 * DIM_ / 32, DIM_ / 32), wblk>>>(qkv_w,  wqkv,  DIM_, 3 * DIM_);
    wprep<<<dim3(DIM_ / 32,     DIM_ / 32), wblk>>>(proj_w, wproj, DIM_, DIM_);
    wprep<<<dim3(HIDDEN_ / 32,  DIM_ / 32), wblk>>>(fc1_w,  wfc1,  DIM_, HIDDEN_);
    wprep<<<dim3(DIM_ / 32, HIDDEN_ / 32),  wblk>>>(fc2_w,  wfc2,  HIDDEN_, DIM_);

    // 1) LN1 -> bf16
    ln_kernel<<<ROWS_, 256>>>(x, ln1_g, ln1_b, h_bf);

    // 2) QKV GEMM (wide tile)
    bgemm_wide<false, false><<<dim3(3 * DIM_ / 256, ROWS_ / 128), 256, WGEMM_SMEM>>>(
        h_bf, DIM_, wqkv, DIM_, qkv, 3 * DIM_, nullptr, nullptr, DIM_);

    // 2b) V^T bf16 prep
    vt_prep<<<dim3(BH_, N_ / 64), 256>>>(qkv, vt);

    // 3) fused attention -> bf16 o
    flash_attn_kernel<<<dim3(BH_, N_ / 128), 256, FLASH_SMEM>>>(qkv, vt, rpe, o_bf);

    // 4) proj + bias + residual(x) -> fp32 x1
    bgemm<false, false><<<dim3(DIM_ / 128, ROWS_ / 128), 256, BGEMM_SMEM>>>(
        o_bf, DIM_, wproj, DIM_, x1, DIM_, proj_b, x, DIM_);

    // 5) LN2 -> bf16
    ln_kernel<<<ROWS_, 256>>>(x1, ln2_g, ln2_b, h_bf);

    // 6) FC1 + bias + gelu -> bf16 mlp (wide tile)
    bgemm_wide<true, true><<<dim3(HIDDEN_ / 256, ROWS_ / 128), 256, WGEMM_SMEM>>>(
        h_bf, DIM_, wfc1, DIM_, mlp, HIDDEN_, fc1_b, nullptr, DIM_);

    // 7) FC2 + bias + residual(x1) -> out fp32
    bgemm<false, false><<<dim3(DIM_ / 128, ROWS_ / 128), 256, BGEMM_SMEM>>>(
        mlp, HIDDEN_, wfc2, HIDDEN_, out, DIM_, fc2_b, x1, HIDDEN_);
}